// round 11
// baseline (speedup 1.0000x reference)
#include <cuda_runtime.h>
#include <cstdint>

// ---------------- problem constants ----------------
#define BATCH   32
#define NTOK    1024
#define DDIM    1024
#define MFF     4096
#define LN_EPS  1e-5f

#define MS_SPLIT 16
#define F1_SPLIT 16
#define F2_SPLIT 64

// ---------------- scratch ----------------
__device__ float g_x    [BATCH * NTOK];
__device__ float g_qstat[64];                 // (mean, rstd) per Q row
__device__ float g_xraw [64];                 // (sum, sumsq) per x row (atomics)
__device__ float g_part [4194304];            // split-K partials (16 MB)

#define MU_OFF  0                             // 16*32*1024 = 524288
#define SIG_OFF 524288
#define W1_OFF  0                             // 16*32*4096 = 2097152 (reuses mu/sig)
#define W2_OFF  2097152                       // 64*32*1024 = 2097152

// dynamic smem: W [128][68] + A [32][68], both k-major
#define GEMM_SMEM ((128 * 68 + 32 * 68) * 4)  // 43520 B -> 4 blocks/SM

__device__ __forceinline__ uint32_t smem_u32(const void* p)
{
    return (uint32_t)__cvta_generic_to_shared(p);
}
#define CP_ASYNC16(dst, src) \
    asm volatile("cp.async.ca.shared.global [%0], [%1], 16;\n" \
                 :: "r"(dst), "l"(src))

// =====================================================================
// Q row stats (mean, rstd) + zero the x-stat accumulators. 1 block.
// =====================================================================
__global__ void stats_kernel(const float* __restrict__ Q)
{
    const int tid = threadIdx.x;
    if (tid < 64) g_xraw[tid] = 0.f;
    const int r = tid >> 5, lane = tid & 31;
    const float4* p = reinterpret_cast<const float4*>(Q + r * NTOK);
    float s = 0.f, ss = 0.f;
    #pragma unroll
    for (int i = 0; i < 8; ++i) {
        float4 v = p[lane + 32 * i];
        s  += v.x + v.y + v.z + v.w;
        ss += v.x*v.x + v.y*v.y + v.z*v.z + v.w*v.w;
    }
    #pragma unroll
    for (int o = 16; o; o >>= 1) {
        s  += __shfl_xor_sync(0xffffffffu, s,  o);
        ss += __shfl_xor_sync(0xffffffffu, ss, o);
    }
    if (lane == 0) {
        const float mean = s * (1.0f / NTOK);
        const float var  = ss * (1.0f / NTOK) - mean * mean;
        g_qstat[2 * r]     = mean;
        g_qstat[2 * r + 1] = rsqrtf(var + LN_EPS);
    }
}

// =====================================================================
// Split-K GEMM, k-pair-packed FFMA2 (acc = (sum even k, sum odd k)).
// Block tile 32(M) x 128(N); K strip 64; 256 threads; thread tile
// 8m x 2n (n strided by 64). 43.5 KB smem + 64 regs -> 4 blocks/SM
// (32 warps). Both panels k-major, rows padded to 68 floats (17x16B,
// odd -> conflict-free strided LDS.128). W fetched via cp.async in two
// 32-k chunks (chunk 1 overlaps compute of chunk 0). Inner loop per
// k-quad: 2 LDS.128 (W) + 8 broadcast LDS.128 (A) + 32 fma.f32x2.
// AMODE 0: A = LN(Q) (g_qstat)  1: A = LN(g_x) (g_xraw)
// AMODE 2: A = silu(sum of F1_SPLIT partials + b1)
// gridDim = (N/128, nsplit, nz); z selects W0/W1 (mu/sigma fusion).
// =====================================================================
template<int AMODE>
__global__ __launch_bounds__(256, 4)
void gemm_kernel(const float* __restrict__ W0, const float* __restrict__ W1,
                 int ldw, int N, int partOff, int partStrideZ,
                 const float* __restrict__ Ain,
                 const float* __restrict__ lng, const float* __restrict__ lnb,
                 const float* __restrict__ b1)
{
    extern __shared__ __align__(16) float smem[];
    float* w_s = smem;              // [128 n][68] k-major
    float* a_s = smem + 128 * 68;   // [32 m][68]  k-major

    const int tid = threadIdx.x;
    const float* __restrict__ W = (blockIdx.z == 0) ? W0 : W1;
    float* __restrict__ P = g_part + partOff + (size_t)blockIdx.z * partStrideZ;

    const int j0    = blockIdx.x * 128;
    const int split = blockIdx.y;
    const int kOff  = split * 64;

    // ---- async W fetch: 2 chunks x 4 quads/thread, coalesced ----
    const uint32_t wbase = smem_u32(w_s);
    #pragma unroll
    for (int c = 0; c < 2; ++c) {
        #pragma unroll
        for (int j = 0; j < 4; ++j) {
            const int idx = j * 256 + tid;
            const int n   = idx >> 3;            // 0..127
            const int kq  = (idx & 7) + c * 8;
            const float* src = W + (size_t)(j0 + n) * ldw + kOff + kq * 4;
            CP_ASYNC16(wbase + (uint32_t)((n * 68 + kq * 4) * 4), src);
        }
        asm volatile("cp.async.commit_group;\n");
    }

    // ---- A panel build (overlaps with W in flight): 2 quads/thread ----
    #pragma unroll
    for (int t = 0; t < 2; ++t) {
        const int idx = t * 256 + tid;
        const int ra  = idx >> 4;          // 0..31
        const int kq  = idx & 15;
        const int kc  = kOff + kq * 4;
        float4 av;
        if (AMODE < 2) {
            float mean, rs;
            if (AMODE == 0) { mean = g_qstat[2 * ra]; rs = g_qstat[2 * ra + 1]; }
            else {
                const float s  = g_xraw[2 * ra];
                const float ss = g_xraw[2 * ra + 1];
                mean = s * (1.0f / NTOK);
                rs   = rsqrtf(ss * (1.0f / NTOK) - mean * mean + LN_EPS);
            }
            const float* Arow = (AMODE == 1) ? (g_x + ra * NTOK) : (Ain + ra * NTOK);
            const float4 fa = *reinterpret_cast<const float4*>(Arow + kc);
            const float4 fg = *reinterpret_cast<const float4*>(lng + kc);
            const float4 fb = *reinterpret_cast<const float4*>(lnb + kc);
            av.x = (fa.x - mean) * rs * fg.x + fb.x;
            av.y = (fa.y - mean) * rs * fg.y + fb.y;
            av.z = (fa.z - mean) * rs * fg.z + fb.z;
            av.w = (fa.w - mean) * rs * fg.w + fb.w;
        } else {
            float4 v = *reinterpret_cast<const float4*>(b1 + kc);
            #pragma unroll
            for (int s = 0; s < F1_SPLIT; ++s) {
                const float4 p = *reinterpret_cast<const float4*>(
                    g_part + W1_OFF + (size_t)(s * BATCH + ra) * MFF + kc);
                v.x += p.x; v.y += p.y; v.z += p.z; v.w += p.w;
            }
            av.x = v.x / (1.0f + __expf(-v.x));
            av.y = v.y / (1.0f + __expf(-v.y));
            av.z = v.z / (1.0f + __expf(-v.z));
            av.w = v.w / (1.0f + __expf(-v.w));
        }
        *reinterpret_cast<float4*>(&a_s[ra * 68 + kq * 4]) = av;
    }

    // ---- compute ----
    const int tx = tid & 63, ty = tid >> 6;    // n: tx+64*ni, m: 8*ty+mi

    unsigned long long acc[8][2];
    #pragma unroll
    for (int mi = 0; mi < 8; ++mi) { acc[mi][0] = 0ull; acc[mi][1] = 0ull; }

    #pragma unroll
    for (int half = 0; half < 2; ++half) {
        if (half == 0) asm volatile("cp.async.wait_group 1;\n");
        else           asm volatile("cp.async.wait_group 0;\n");
        __syncthreads();
        #pragma unroll
        for (int kq = half * 8; kq < half * 8 + 8; ++kq) {
            ulonglong2 wv[2];
            #pragma unroll
            for (int ni = 0; ni < 2; ++ni)
                wv[ni] = *reinterpret_cast<const ulonglong2*>(
                    &w_s[(tx + 64 * ni) * 68 + kq * 4]);
            #pragma unroll
            for (int mi = 0; mi < 8; ++mi) {
                const ulonglong2 avv = *reinterpret_cast<const ulonglong2*>(
                    &a_s[(8 * ty + mi) * 68 + kq * 4]);
                #pragma unroll
                for (int ni = 0; ni < 2; ++ni) {
                    asm("fma.rn.f32x2 %0, %1, %2, %0;"
                        : "+l"(acc[mi][ni]) : "l"(avv.x), "l"(wv[ni].x));
                    asm("fma.rn.f32x2 %0, %1, %2, %0;"
                        : "+l"(acc[mi][ni]) : "l"(avv.y), "l"(wv[ni].y));
                }
            }
        }
    }

    // ---- epilogue: fold (even,odd); m = 8ty+mi, n = j0+tx+64ni ----
    #pragma unroll
    for (int mi = 0; mi < 8; ++mi) {
        float* dst = P + (size_t)(split * BATCH + 8 * ty + mi) * N + j0;
        #pragma unroll
        for (int ni = 0; ni < 2; ++ni) {
            float lo, hi;
            asm("mov.b64 {%0, %1}, %2;" : "=f"(lo), "=f"(hi) : "l"(acc[mi][ni]));
            dst[tx + 64 * ni] = lo + hi;
        }
    }
}

// =====================================================================
// Gaussian pseudo-attention: one warp per (b,i), streams K/V (256 MB)
// with all 16 row loads batched up front (MLP=16). Folds mu/sigma
// split-K combine; accumulates LN(x) stats via atomics.
// =====================================================================
__global__ __launch_bounds__(256)
void gauss_kernel(const float* __restrict__ Kp,
                  const float* __restrict__ Vp,
                  const float* __restrict__ Qp,
                  const float* __restrict__ mu_b,
                  const float* __restrict__ sig_b)
{
    const int tid  = threadIdx.x;
    const int w    = blockIdx.x * 8 + (tid >> 5);
    const int lane = tid & 31;
    const int b = w >> 10;
    const int i = w & 1023;

    float mu = mu_b[i];
    float sg = sig_b[i];
    #pragma unroll
    for (int s = 0; s < MS_SPLIT; ++s) {
        mu += g_part[MU_OFF  + (s * BATCH + b) * NTOK + i];
        sg += g_part[SIG_OFF + (s * BATCH + b) * NTOK + i];
    }
    mu = tanhf(mu);
    const float coef = -0.5f / (sg * sg + 1e-8f);

    const float4* K4 = reinterpret_cast<const float4*>(Kp) + (size_t)w * (DDIM / 4);
    const float4* V4 = reinterpret_cast<const float4*>(Vp) + (size_t)w * (DDIM / 4);

    float4 kr[8], vr[8];
    #pragma unroll
    for (int it = 0; it < 8; ++it) kr[it] = __ldcs(&K4[it * 32 + lane]);
    #pragma unroll
    for (int it = 0; it < 8; ++it) vr[it] = __ldcs(&V4[it * 32 + lane]);

    float acc = 0.f;
    #pragma unroll
    for (int it = 0; it < 8; ++it) {
        float d;
        d = kr[it].x - mu; acc += __expf(coef * d * d) * vr[it].x;
        d = kr[it].y - mu; acc += __expf(coef * d * d) * vr[it].y;
        d = kr[it].z - mu; acc += __expf(coef * d * d) * vr[it].z;
        d = kr[it].w - mu; acc += __expf(coef * d * d) * vr[it].w;
    }
    #pragma unroll
    for (int o = 16; o; o >>= 1) acc += __shfl_xor_sync(0xffffffffu, acc, o);

    __shared__ float shv[8];
    if (lane == 0) {
        const float v = acc + Qp[w];
        g_x[w] = v;
        shv[tid >> 5] = v;
    }
    __syncthreads();
    if (tid < 32) {
        float v = (lane < 8) ? shv[lane] : 0.f;
        float s = v, ss = v * v;
        #pragma unroll
        for (int o = 4; o; o >>= 1) {
            s  += __shfl_xor_sync(0xffffffffu, s,  o);
            ss += __shfl_xor_sync(0xffffffffu, ss, o);
        }
        if (lane == 0) {
            atomicAdd(&g_xraw[2 * b],     s);
            atomicAdd(&g_xraw[2 * b + 1], ss);
        }
    }
}

// =====================================================================
// final combine: out = x + b2 + sum of F2_SPLIT partials   (32 x 1024)
// =====================================================================
__global__ void final_kernel(const float* __restrict__ b2,
                             float* __restrict__ out)
{
    const int t  = blockIdx.x * blockDim.x + threadIdx.x;   // 0..8191 float4s
    const int m  = t >> 8;
    const int j4 = t & 255;
    float4 s = reinterpret_cast<const float4*>(g_x)[t];
    const float4 bb = reinterpret_cast<const float4*>(b2)[j4];
    s.x += bb.x; s.y += bb.y; s.z += bb.z; s.w += bb.w;
    #pragma unroll
    for (int sp = 0; sp < F2_SPLIT; ++sp) {
        const float4 p = *reinterpret_cast<const float4*>(
            g_part + W2_OFF + (size_t)(sp * BATCH + m) * NTOK + j4 * 4);
        s.x += p.x; s.y += p.y; s.z += p.z; s.w += p.w;
    }
    reinterpret_cast<float4*>(out)[t] = s;
}

// =====================================================================
extern "C" void kernel_launch(void* const* d_in, const int* in_sizes, int n_in,
                              void* d_out, int out_size)
{
    const float* Q       = (const float*)d_in[0];
    const float* Kt      = (const float*)d_in[1];
    const float* Vt      = (const float*)d_in[2];
    const float* mu_w    = (const float*)d_in[3];
    const float* mu_b    = (const float*)d_in[4];
    const float* sigma_w = (const float*)d_in[5];
    const float* sigma_b = (const float*)d_in[6];
    const float* ffn_w1  = (const float*)d_in[7];
    const float* ffn_b1  = (const float*)d_in[8];
    const float* ffn_w2  = (const float*)d_in[9];
    const float* ffn_b2  = (const float*)d_in[10];
    const float* ln_ff_g = (const float*)d_in[11];
    const float* ln_ff_b = (const float*)d_in[12];
    const float* ln_q_g  = (const float*)d_in[13];
    const float* ln_q_b  = (const float*)d_in[14];
    float* out = (float*)d_out;

    cudaFuncSetAttribute(gemm_kernel<0>,
                         cudaFuncAttributeMaxDynamicSharedMemorySize, GEMM_SMEM);
    cudaFuncSetAttribute(gemm_kernel<1>,
                         cudaFuncAttributeMaxDynamicSharedMemorySize, GEMM_SMEM);
    cudaFuncSetAttribute(gemm_kernel<2>,
                         cudaFuncAttributeMaxDynamicSharedMemorySize, GEMM_SMEM);

    // 1. Q row stats + zero x-stat accumulators
    stats_kernel<<<1, 1024>>>(Q);

    // 2. mu & sigma partial GEMMs on LN(Q), split-K 16, z selects matrix
    gemm_kernel<0><<<dim3(NTOK / 128, MS_SPLIT, 2), 256, GEMM_SMEM>>>(
        mu_w, sigma_w, NTOK, NTOK, MU_OFF, SIG_OFF - MU_OFF,
        Q, ln_q_g, ln_q_b, nullptr);

    // 3. Gaussian stream + mu/sigma combine + x-stat atomics
    gauss_kernel<<<(BATCH * NTOK) / 8, 256>>>(Kt, Vt, Q, mu_b, sigma_b);

    // 4. FFN GEMM 1 on LN(g_x), split-K 16 -> 512 blocks
    gemm_kernel<1><<<dim3(MFF / 128, F1_SPLIT, 1), 256, GEMM_SMEM>>>(
        ffn_w1, ffn_w1, NTOK, MFF, W1_OFF, 0,
        nullptr, ln_ff_g, ln_ff_b, nullptr);

    // 5. FFN GEMM 2 on silu(partials + b1), split-K 64 -> 512 blocks
    gemm_kernel<2><<<dim3(NTOK / 128, F2_SPLIT, 1), 256, GEMM_SMEM>>>(
        ffn_w2, ffn_w2, MFF, NTOK, W2_OFF, 0,
        nullptr, nullptr, nullptr, ffn_b1);

    // 6. out = x + b2 + sum of FFN2 partials
    final_kernel<<<64, 128>>>(ffn_b2, out);
}

// round 12
// speedup vs baseline: 1.0418x; 1.0418x over previous
#include <cuda_runtime.h>
#include <cstdint>

// ---------------- problem constants ----------------
#define BATCH   32
#define NTOK    1024
#define DDIM    1024
#define MFF     4096
#define LN_EPS  1e-5f

#define MS_SPLIT 8
#define F1_SPLIT 8
#define F2_SPLIT 32

// ---------------- scratch ----------------
__device__ float g_x    [BATCH * NTOK];
__device__ float g_qstat[64];                 // (mean, rstd) per Q row
__device__ float g_xraw [64];                 // (sum, sumsq) per x row (atomics)
__device__ float g_part [2097152];            // split-K partials (8 MB)

#define MU_OFF  0                             // 8*32*1024 = 262144
#define SIG_OFF 262144
#define W1_OFF  0                             // 8*32*4096 = 1048576 (reuses mu/sig)
#define W2_OFF  1048576                       // 32*32*1024 = 1048576

// dynamic smem: W [2 strips][256 n][68] + A [2 strips][32 m][68]
#define GEMM_SMEM ((2 * 256 * 68 + 2 * 32 * 68) * 4)   // 156672 B -> 1 block/SM

__device__ __forceinline__ uint32_t smem_u32(const void* p)
{
    return (uint32_t)__cvta_generic_to_shared(p);
}
#define CP_ASYNC16(dst, src) \
    asm volatile("cp.async.ca.shared.global [%0], [%1], 16;\n" \
                 :: "r"(dst), "l"(src))

// =====================================================================
// Q row stats (mean, rstd) + zero the x-stat accumulators. 1 block.
// =====================================================================
__global__ void stats_kernel(const float* __restrict__ Q)
{
    const int tid = threadIdx.x;
    if (tid < 64) g_xraw[tid] = 0.f;
    const int r = tid >> 5, lane = tid & 31;
    const float4* p = reinterpret_cast<const float4*>(Q + r * NTOK);
    float s = 0.f, ss = 0.f;
    #pragma unroll
    for (int i = 0; i < 8; ++i) {
        float4 v = p[lane + 32 * i];
        s  += v.x + v.y + v.z + v.w;
        ss += v.x*v.x + v.y*v.y + v.z*v.z + v.w*v.w;
    }
    #pragma unroll
    for (int o = 16; o; o >>= 1) {
        s  += __shfl_xor_sync(0xffffffffu, s,  o);
        ss += __shfl_xor_sync(0xffffffffu, ss, o);
    }
    if (lane == 0) {
        const float mean = s * (1.0f / NTOK);
        const float var  = ss * (1.0f / NTOK) - mean * mean;
        g_qstat[2 * r]     = mean;
        g_qstat[2 * r + 1] = rsqrtf(var + LN_EPS);
    }
}

// =====================================================================
// Split-K GEMM, k-pair-packed FFMA2. Block tile 32(M) x 256(N), K strip
// 128 = 2 x 64 in two separate smem buffers. Both cp.async bursts issued
// up front (2 commit groups) -> strip 1 streams from DRAM while strip 0
// computes. 256 threads, thread tile 8m x 4n (n strided by 64; rows
// padded to 68 floats = 17 x 16B, odd -> conflict-free LDS.128).
// Inner loop per k-quad: 4 LDS.128 (W) + 8 broadcast LDS.128 (A) +
// 64 fma.f32x2 -> fma pipe saturated by 8 warps.
// AMODE 0: A = LN(Q) (g_qstat)  1: A = LN(g_x) (g_xraw)
// AMODE 2: A = silu(sum of F1_SPLIT partials + b1)
// gridDim = (N/256, nsplit, nz); z selects W0/W1 (mu/sigma fusion).
// =====================================================================
template<int AMODE>
__global__ __launch_bounds__(256)
void gemm_kernel(const float* __restrict__ W0, const float* __restrict__ W1,
                 int ldw, int N, int partOff, int partStrideZ,
                 const float* __restrict__ Ain,
                 const float* __restrict__ lng, const float* __restrict__ lnb,
                 const float* __restrict__ b1)
{
    extern __shared__ __align__(16) float smem[];
    float* w_s = smem;                   // [2][256][68] k-major
    float* a_s = smem + 2 * 256 * 68;    // [2][32][68]  k-major

    const int tid = threadIdx.x;
    const float* __restrict__ W = (blockIdx.z == 0) ? W0 : W1;
    float* __restrict__ P = g_part + partOff + (size_t)blockIdx.z * partStrideZ;

    const int j0    = blockIdx.x * 256;
    const int split = blockIdx.y;
    const int kOff  = split * 128;

    // ---- issue BOTH strips' cp.async bursts up front ----
    const uint32_t wbase = smem_u32(w_s);
    #pragma unroll
    for (int c = 0; c < 2; ++c) {
        #pragma unroll
        for (int j = 0; j < 16; ++j) {
            const int idx = j * 256 + tid;
            const int n   = idx >> 4;            // 0..255
            const int kq  = idx & 15;            // 0..15
            const float* src = W + (size_t)(j0 + n) * ldw + kOff + c * 64 + kq * 4;
            CP_ASYNC16(wbase + (uint32_t)((c * 256 * 68 + n * 68 + kq * 4) * 4), src);
        }
        asm volatile("cp.async.commit_group;\n");
    }

    // ---- A panel build for both strips (overlaps W streaming) ----
    #pragma unroll
    for (int t = 0; t < 4; ++t) {
        const int idx = t * 256 + tid;           // 0..1023
        const int ra  = idx >> 5;                // 0..31
        const int q   = idx & 31;                // 0..31 (both strips)
        const int c   = q >> 4;
        const int kq  = q & 15;
        const int kc  = kOff + c * 64 + kq * 4;
        float4 av;
        if (AMODE < 2) {
            float mean, rs;
            if (AMODE == 0) { mean = g_qstat[2 * ra]; rs = g_qstat[2 * ra + 1]; }
            else {
                const float s  = g_xraw[2 * ra];
                const float ss = g_xraw[2 * ra + 1];
                mean = s * (1.0f / NTOK);
                rs   = rsqrtf(ss * (1.0f / NTOK) - mean * mean + LN_EPS);
            }
            const float* Arow = (AMODE == 1) ? (g_x + ra * NTOK) : (Ain + ra * NTOK);
            const float4 fa = *reinterpret_cast<const float4*>(Arow + kc);
            const float4 fg = *reinterpret_cast<const float4*>(lng + kc);
            const float4 fb = *reinterpret_cast<const float4*>(lnb + kc);
            av.x = (fa.x - mean) * rs * fg.x + fb.x;
            av.y = (fa.y - mean) * rs * fg.y + fb.y;
            av.z = (fa.z - mean) * rs * fg.z + fb.z;
            av.w = (fa.w - mean) * rs * fg.w + fb.w;
        } else {
            float4 v = *reinterpret_cast<const float4*>(b1 + kc);
            #pragma unroll
            for (int s = 0; s < F1_SPLIT; ++s) {
                const float4 p = *reinterpret_cast<const float4*>(
                    g_part + W1_OFF + (size_t)(s * BATCH + ra) * MFF + kc);
                v.x += p.x; v.y += p.y; v.z += p.z; v.w += p.w;
            }
            av.x = v.x / (1.0f + __expf(-v.x));
            av.y = v.y / (1.0f + __expf(-v.y));
            av.z = v.z / (1.0f + __expf(-v.z));
            av.w = v.w / (1.0f + __expf(-v.w));
        }
        *reinterpret_cast<float4*>(&a_s[c * 32 * 68 + ra * 68 + kq * 4]) = av;
    }

    // ---- compute: strip 0 while strip 1 streams, then strip 1 ----
    const int tx = tid & 63, ty = tid >> 6;      // n: tx+64*ni, m: 8*ty+mi

    unsigned long long acc[8][4];
    #pragma unroll
    for (int mi = 0; mi < 8; ++mi)
        #pragma unroll
        for (int ni = 0; ni < 4; ++ni) acc[mi][ni] = 0ull;

    #pragma unroll
    for (int c = 0; c < 2; ++c) {
        if (c == 0) asm volatile("cp.async.wait_group 1;\n");
        else        asm volatile("cp.async.wait_group 0;\n");
        __syncthreads();
        const float* wsc = w_s + c * 256 * 68;
        const float* asc = a_s + c * 32 * 68;
        #pragma unroll
        for (int kq = 0; kq < 16; ++kq) {
            ulonglong2 wv[4];
            #pragma unroll
            for (int ni = 0; ni < 4; ++ni)
                wv[ni] = *reinterpret_cast<const ulonglong2*>(
                    &wsc[(tx + 64 * ni) * 68 + kq * 4]);
            #pragma unroll
            for (int mi = 0; mi < 8; ++mi) {
                const ulonglong2 avv = *reinterpret_cast<const ulonglong2*>(
                    &asc[(8 * ty + mi) * 68 + kq * 4]);
                #pragma unroll
                for (int ni = 0; ni < 4; ++ni) {
                    asm("fma.rn.f32x2 %0, %1, %2, %0;"
                        : "+l"(acc[mi][ni]) : "l"(avv.x), "l"(wv[ni].x));
                    asm("fma.rn.f32x2 %0, %1, %2, %0;"
                        : "+l"(acc[mi][ni]) : "l"(avv.y), "l"(wv[ni].y));
                }
            }
        }
    }

    // ---- epilogue: fold (even,odd); m = 8ty+mi, n = j0+tx+64ni ----
    #pragma unroll
    for (int mi = 0; mi < 8; ++mi) {
        float* dst = P + (size_t)(split * BATCH + 8 * ty + mi) * N + j0;
        #pragma unroll
        for (int ni = 0; ni < 4; ++ni) {
            float lo, hi;
            asm("mov.b64 {%0, %1}, %2;" : "=f"(lo), "=f"(hi) : "l"(acc[mi][ni]));
            dst[tx + 64 * ni] = lo + hi;
        }
    }
}

// =====================================================================
// Gaussian pseudo-attention: one warp per (b,i), streams K/V (256 MB)
// with all 16 row loads batched up front (MLP=16). Folds mu/sigma
// split-K combine; accumulates LN(x) stats via atomics.
// =====================================================================
__global__ __launch_bounds__(256)
void gauss_kernel(const float* __restrict__ Kp,
                  const float* __restrict__ Vp,
                  const float* __restrict__ Qp,
                  const float* __restrict__ mu_b,
                  const float* __restrict__ sig_b)
{
    const int tid  = threadIdx.x;
    const int w    = blockIdx.x * 8 + (tid >> 5);
    const int lane = tid & 31;
    const int b = w >> 10;
    const int i = w & 1023;

    float mu = mu_b[i];
    float sg = sig_b[i];
    #pragma unroll
    for (int s = 0; s < MS_SPLIT; ++s) {
        mu += g_part[MU_OFF  + (s * BATCH + b) * NTOK + i];
        sg += g_part[SIG_OFF + (s * BATCH + b) * NTOK + i];
    }
    mu = tanhf(mu);
    const float coef = -0.5f / (sg * sg + 1e-8f);

    const float4* K4 = reinterpret_cast<const float4*>(Kp) + (size_t)w * (DDIM / 4);
    const float4* V4 = reinterpret_cast<const float4*>(Vp) + (size_t)w * (DDIM / 4);

    float4 kr[8], vr[8];
    #pragma unroll
    for (int it = 0; it < 8; ++it) kr[it] = __ldcs(&K4[it * 32 + lane]);
    #pragma unroll
    for (int it = 0; it < 8; ++it) vr[it] = __ldcs(&V4[it * 32 + lane]);

    float acc = 0.f;
    #pragma unroll
    for (int it = 0; it < 8; ++it) {
        float d;
        d = kr[it].x - mu; acc += __expf(coef * d * d) * vr[it].x;
        d = kr[it].y - mu; acc += __expf(coef * d * d) * vr[it].y;
        d = kr[it].z - mu; acc += __expf(coef * d * d) * vr[it].z;
        d = kr[it].w - mu; acc += __expf(coef * d * d) * vr[it].w;
    }
    #pragma unroll
    for (int o = 16; o; o >>= 1) acc += __shfl_xor_sync(0xffffffffu, acc, o);

    __shared__ float shv[8];
    if (lane == 0) {
        const float v = acc + Qp[w];
        g_x[w] = v;
        shv[tid >> 5] = v;
    }
    __syncthreads();
    if (tid < 32) {
        float v = (lane < 8) ? shv[lane] : 0.f;
        float s = v, ss = v * v;
        #pragma unroll
        for (int o = 4; o; o >>= 1) {
            s  += __shfl_xor_sync(0xffffffffu, s,  o);
            ss += __shfl_xor_sync(0xffffffffu, ss, o);
        }
        if (lane == 0) {
            atomicAdd(&g_xraw[2 * b],     s);
            atomicAdd(&g_xraw[2 * b + 1], ss);
        }
    }
}

// =====================================================================
// final combine: out = x + b2 + sum of F2_SPLIT partials   (32 x 1024)
// =====================================================================
__global__ void final_kernel(const float* __restrict__ b2,
                             float* __restrict__ out)
{
    const int t  = blockIdx.x * blockDim.x + threadIdx.x;   // 0..8191 float4s
    const int m  = t >> 8;
    const int j4 = t & 255;
    float4 s = reinterpret_cast<const float4*>(g_x)[t];
    const float4 bb = reinterpret_cast<const float4*>(b2)[j4];
    s.x += bb.x; s.y += bb.y; s.z += bb.z; s.w += bb.w;
    #pragma unroll
    for (int sp = 0; sp < F2_SPLIT; ++sp) {
        const float4 p = *reinterpret_cast<const float4*>(
            g_part + W2_OFF + (size_t)(sp * BATCH + m) * NTOK + j4 * 4);
        s.x += p.x; s.y += p.y; s.z += p.z; s.w += p.w;
    }
    reinterpret_cast<float4*>(out)[t] = s;
}

// =====================================================================
extern "C" void kernel_launch(void* const* d_in, const int* in_sizes, int n_in,
                              void* d_out, int out_size)
{
    const float* Q       = (const float*)d_in[0];
    const float* Kt      = (const float*)d_in[1];
    const float* Vt      = (const float*)d_in[2];
    const float* mu_w    = (const float*)d_in[3];
    const float* mu_b    = (const float*)d_in[4];
    const float* sigma_w = (const float*)d_in[5];
    const float* sigma_b = (const float*)d_in[6];
    const float* ffn_w1  = (const float*)d_in[7];
    const float* ffn_b1  = (const float*)d_in[8];
    const float* ffn_w2  = (const float*)d_in[9];
    const float* ffn_b2  = (const float*)d_in[10];
    const float* ln_ff_g = (const float*)d_in[11];
    const float* ln_ff_b = (const float*)d_in[12];
    const float* ln_q_g  = (const float*)d_in[13];
    const float* ln_q_b  = (const float*)d_in[14];
    float* out = (float*)d_out;

    cudaFuncSetAttribute(gemm_kernel<0>,
                         cudaFuncAttributeMaxDynamicSharedMemorySize, GEMM_SMEM);
    cudaFuncSetAttribute(gemm_kernel<1>,
                         cudaFuncAttributeMaxDynamicSharedMemorySize, GEMM_SMEM);
    cudaFuncSetAttribute(gemm_kernel<2>,
                         cudaFuncAttributeMaxDynamicSharedMemorySize, GEMM_SMEM);

    // 1. Q row stats + zero x-stat accumulators
    stats_kernel<<<1, 1024>>>(Q);

    // 2. mu & sigma partial GEMMs on LN(Q), split-K 8 (128k pipelined)
    gemm_kernel<0><<<dim3(NTOK / 256, MS_SPLIT, 2), 256, GEMM_SMEM>>>(
        mu_w, sigma_w, NTOK, NTOK, MU_OFF, SIG_OFF - MU_OFF,
        Q, ln_q_g, ln_q_b, nullptr);

    // 3. Gaussian stream + mu/sigma combine + x-stat atomics
    gauss_kernel<<<(BATCH * NTOK) / 8, 256>>>(Kt, Vt, Q, mu_b, sigma_b);

    // 4. FFN GEMM 1 on LN(g_x), split-K 8 -> 128 blocks (one wave)
    gemm_kernel<1><<<dim3(MFF / 256, F1_SPLIT, 1), 256, GEMM_SMEM>>>(
        ffn_w1, ffn_w1, NTOK, MFF, W1_OFF, 0,
        nullptr, ln_ff_g, ln_ff_b, nullptr);

    // 5. FFN GEMM 2 on silu(partials + b1), split-K 32 -> 128 blocks
    gemm_kernel<2><<<dim3(NTOK / 256, F2_SPLIT, 1), 256, GEMM_SMEM>>>(
        ffn_w2, ffn_w2, MFF, NTOK, W2_OFF, 0,
        nullptr, nullptr, nullptr, ffn_b1);

    // 6. out = x + b2 + sum of FFN2 partials
    final_kernel<<<64, 128>>>(ffn_b2, out);
}

// round 14
// speedup vs baseline: 1.0578x; 1.0154x over previous
#include <cuda_runtime.h>
#include <cstdint>

// ---------------- problem constants ----------------
#define BATCH   32
#define NTOK    1024
#define DDIM    1024
#define MFF     4096
#define LN_EPS  1e-5f

#define MS_SPLIT 32
#define F1_SPLIT 16
#define F2_SPLIT 64

// ---------------- scratch ----------------
__device__ float g_x    [BATCH * NTOK];
__device__ float g_qstat[64];                 // (mean, rstd) per Q row
__device__ float g_xraw [64];                 // (sum, sumsq) per x row (atomics)
__device__ float g_part [4194304];            // split-K partials (16 MB)

#define MU_OFF  0                             // 32*32*1024 = 1048576
#define SIG_OFF 1048576
#define W1_OFF  0                             // 16*32*4096 = 2097152 (reuses mu/sig)
#define W2_OFF  2097152                       // 64*32*1024 = 2097152

// dynamic smem for KQ k-quads: (256 + 32) rows x (4KQ+4) floats
#define GEMM_SMEM(KQ) ((256 + 32) * (4 * (KQ) + 4) * 4)

__device__ __forceinline__ uint32_t smem_u32(const void* p)
{
    return (uint32_t)__cvta_generic_to_shared(p);
}
#define CP_ASYNC16(dst, src) \
    asm volatile("cp.async.ca.shared.global [%0], [%1], 16;\n" \
                 :: "r"(dst), "l"(src))

// =====================================================================
// Q row stats (mean, rstd) + zero the x-stat accumulators. 1 block.
// =====================================================================
__global__ void stats_kernel(const float* __restrict__ Q)
{
    const int tid = threadIdx.x;
    if (tid < 64) g_xraw[tid] = 0.f;
    const int r = tid >> 5, lane = tid & 31;
    const float4* p = reinterpret_cast<const float4*>(Q + r * NTOK);
    float s = 0.f, ss = 0.f;
    #pragma unroll
    for (int i = 0; i < 8; ++i) {
        float4 v = p[lane + 32 * i];
        s  += v.x + v.y + v.z + v.w;
        ss += v.x*v.x + v.y*v.y + v.z*v.z + v.w*v.w;
    }
    #pragma unroll
    for (int o = 16; o; o >>= 1) {
        s  += __shfl_xor_sync(0xffffffffu, s,  o);
        ss += __shfl_xor_sync(0xffffffffu, ss, o);
    }
    if (lane == 0) {
        const float mean = s * (1.0f / NTOK);
        const float var  = ss * (1.0f / NTOK) - mean * mean;
        g_qstat[2 * r]     = mean;
        g_qstat[2 * r + 1] = rsqrtf(var + LN_EPS);
    }
}

// =====================================================================
// Split-K GEMM, k-pair-packed FFMA2 (round-10 design, KQ templated).
// Block tile 32(M) x 256(N); K strip = 4*KQ; 256 threads; thread tile
// 8m x 4n (n strided by 64). Rows padded to 4KQ+4 floats (odd x 16B ->
// conflict-free LDS.128). W fetched via cp.async in two half-strips
// (second half streams while first computes). Inner loop per k-quad:
// 4 LDS.128 (W) + 8 broadcast LDS.128 (A) + 64 fma.f32x2 -> fma-bound.
// AMODE 0: A = LN(Q) (g_qstat)  1: A = LN(g_x) (g_xraw)
// AMODE 2: A = silu(sum of F1_SPLIT partials + b1)
// gridDim = (N/256, nsplit, nz); z selects W0/W1 (mu/sigma fusion).
// =====================================================================
template<int AMODE, int KQ>
__global__ __launch_bounds__(256, 2)
void gemm_kernel(const float* __restrict__ W0, const float* __restrict__ W1,
                 int ldw, int N, int partOff, int partStrideZ,
                 const float* __restrict__ Ain,
                 const float* __restrict__ lng, const float* __restrict__ lnb,
                 const float* __restrict__ b1)
{
    constexpr int RS = 4 * KQ + 4;        // row stride in floats
    constexpr int HQ = KQ / 2;            // quads per half-strip

    extern __shared__ __align__(16) float smem[];
    float* w_s = smem;                    // [256 n][RS] k-major
    float* a_s = smem + 256 * RS;         // [32 m][RS]  k-major

    const int tid = threadIdx.x;
    const float* __restrict__ W = (blockIdx.z == 0) ? W0 : W1;
    float* __restrict__ P = g_part + partOff + (size_t)blockIdx.z * partStrideZ;

    const int j0    = blockIdx.x * 256;
    const int split = blockIdx.y;
    const int kOff  = split * (4 * KQ);

    // ---- async W fetch: 2 half-strips, coalesced (HQ quads/thread each) ----
    const uint32_t wbase = smem_u32(w_s);
    #pragma unroll
    for (int c = 0; c < 2; ++c) {
        #pragma unroll
        for (int j = 0; j < HQ; ++j) {
            const int idx = j * 256 + tid;       // 0 .. 256*HQ-1
            const int n   = idx / HQ;            // 0..255
            const int kq  = (idx % HQ) + c * HQ;
            const float* src = W + (size_t)(j0 + n) * ldw + kOff + kq * 4;
            CP_ASYNC16(wbase + (uint32_t)((n * RS + kq * 4) * 4), src);
        }
        asm volatile("cp.async.commit_group;\n");
    }

    // ---- A panel build (overlaps W streaming): KQ/8 quads per thread ----
    #pragma unroll
    for (int t = 0; t < KQ / 8; ++t) {
        const int idx = t * 256 + tid;           // 0 .. 32*KQ-1
        const int ra  = idx / KQ;                // 0..31
        const int kq  = idx % KQ;
        const int kc  = kOff + kq * 4;
        float4 av;
        if (AMODE < 2) {
            float mean, rs;
            if (AMODE == 0) { mean = g_qstat[2 * ra]; rs = g_qstat[2 * ra + 1]; }
            else {
                const float s  = g_xraw[2 * ra];
                const float ss = g_xraw[2 * ra + 1];
                mean = s * (1.0f / NTOK);
                rs   = rsqrtf(ss * (1.0f / NTOK) - mean * mean + LN_EPS);
            }
            const float* Arow = (AMODE == 1) ? (g_x + ra * NTOK) : (Ain + ra * NTOK);
            const float4 fa = *reinterpret_cast<const float4*>(Arow + kc);
            const float4 fg = *reinterpret_cast<const float4*>(lng + kc);
            const float4 fb = *reinterpret_cast<const float4*>(lnb + kc);
            av.x = (fa.x - mean) * rs * fg.x + fb.x;
            av.y = (fa.y - mean) * rs * fg.y + fb.y;
            av.z = (fa.z - mean) * rs * fg.z + fb.z;
            av.w = (fa.w - mean) * rs * fg.w + fb.w;
        } else {
            float4 v = *reinterpret_cast<const float4*>(b1 + kc);
            #pragma unroll
            for (int s = 0; s < F1_SPLIT; ++s) {
                const float4 p = *reinterpret_cast<const float4*>(
                    g_part + W1_OFF + (size_t)(s * BATCH + ra) * MFF + kc);
                v.x += p.x; v.y += p.y; v.z += p.z; v.w += p.w;
            }
            av.x = v.x / (1.0f + __expf(-v.x));
            av.y = v.y / (1.0f + __expf(-v.y));
            av.z = v.z / (1.0f + __expf(-v.z));
            av.w = v.w / (1.0f + __expf(-v.w));
        }
        *reinterpret_cast<float4*>(&a_s[ra * RS + kq * 4]) = av;
    }

    // ---- compute: first half while second streams, then second ----
    const int tx = tid & 63, ty = tid >> 6;      // n: tx+64*ni, m: 8*ty+mi

    unsigned long long acc[8][4];
    #pragma unroll
    for (int mi = 0; mi < 8; ++mi)
        #pragma unroll
        for (int ni = 0; ni < 4; ++ni) acc[mi][ni] = 0ull;

    #pragma unroll
    for (int half = 0; half < 2; ++half) {
        if (half == 0) asm volatile("cp.async.wait_group 1;\n");
        else           asm volatile("cp.async.wait_group 0;\n");
        __syncthreads();
        #pragma unroll
        for (int kq = half * HQ; kq < half * HQ + HQ; ++kq) {
            ulonglong2 wv[4];
            #pragma unroll
            for (int ni = 0; ni < 4; ++ni)
                wv[ni] = *reinterpret_cast<const ulonglong2*>(
                    &w_s[(tx + 64 * ni) * RS + kq * 4]);
            #pragma unroll
            for (int mi = 0; mi < 8; ++mi) {
                const ulonglong2 avv = *reinterpret_cast<const ulonglong2*>(
                    &a_s[(8 * ty + mi) * RS + kq * 4]);
                #pragma unroll
                for (int ni = 0; ni < 4; ++ni) {
                    asm("fma.rn.f32x2 %0, %1, %2, %0;"
                        : "+l"(acc[mi][ni]) : "l"(avv.x), "l"(wv[ni].x));
                    asm("fma.rn.f32x2 %0, %1, %2, %0;"
                        : "+l"(acc[mi][ni]) : "l"(avv.y), "l"(wv[ni].y));
                }
            }
        }
    }

    // ---- epilogue: fold (even,odd); m = 8ty+mi, n = j0+tx+64ni ----
    #pragma unroll
    for (int mi = 0; mi < 8; ++mi) {
        float* dst = P + (size_t)(split * BATCH + 8 * ty + mi) * N + j0;
        #pragma unroll
        for (int ni = 0; ni < 4; ++ni) {
            float lo, hi;
            asm("mov.b64 {%0, %1}, %2;" : "=f"(lo), "=f"(hi) : "l"(acc[mi][ni]));
            dst[tx + 64 * ni] = lo + hi;
        }
    }
}

// =====================================================================
// Gaussian pseudo-attention: one warp per (b,i), streams K/V (256 MB).
// K/V loads issued BEFORE the mu/sigma combine so the stream gets a
// head start; combine folds MS_SPLIT partials; LN(x) stats via atomics.
// =====================================================================
__global__ __launch_bounds__(256)
void gauss_kernel(const float* __restrict__ Kp,
                  const float* __restrict__ Vp,
                  const float* __restrict__ Qp,
                  const float* __restrict__ mu_b,
                  const float* __restrict__ sig_b)
{
    const int tid  = threadIdx.x;
    const int w    = blockIdx.x * 8 + (tid >> 5);
    const int lane = tid & 31;
    const int b = w >> 10;
    const int i = w & 1023;

    const float4* K4 = reinterpret_cast<const float4*>(Kp) + (size_t)w * (DDIM / 4);
    const float4* V4 = reinterpret_cast<const float4*>(Vp) + (size_t)w * (DDIM / 4);

    // issue the big streaming loads first (MLP = 16)
    float4 kr[8], vr[8];
    #pragma unroll
    for (int it = 0; it < 8; ++it) kr[it] = __ldcs(&K4[it * 32 + lane]);
    #pragma unroll
    for (int it = 0; it < 8; ++it) vr[it] = __ldcs(&V4[it * 32 + lane]);

    // combine mu/sigma split-K partials while K/V is in flight
    float mu = mu_b[i];
    float sg = sig_b[i];
    #pragma unroll
    for (int s = 0; s < MS_SPLIT; ++s) {
        mu += g_part[MU_OFF  + (s * BATCH + b) * NTOK + i];
        sg += g_part[SIG_OFF + (s * BATCH + b) * NTOK + i];
    }
    mu = tanhf(mu);
    const float coef = -0.5f / (sg * sg + 1e-8f);

    float acc = 0.f;
    #pragma unroll
    for (int it = 0; it < 8; ++it) {
        float d;
        d = kr[it].x - mu; acc += __expf(coef * d * d) * vr[it].x;
        d = kr[it].y - mu; acc += __expf(coef * d * d) * vr[it].y;
        d = kr[it].z - mu; acc += __expf(coef * d * d) * vr[it].z;
        d = kr[it].w - mu; acc += __expf(coef * d * d) * vr[it].w;
    }
    #pragma unroll
    for (int o = 16; o; o >>= 1) acc += __shfl_xor_sync(0xffffffffu, acc, o);

    __shared__ float shv[8];
    if (lane == 0) {
        const float v = acc + Qp[w];
        g_x[w] = v;
        shv[tid >> 5] = v;
    }
    __syncthreads();
    if (tid < 32) {
        float v = (lane < 8) ? shv[lane] : 0.f;
        float s = v, ss = v * v;
        #pragma unroll
        for (int o = 4; o; o >>= 1) {
            s  += __shfl_xor_sync(0xffffffffu, s,  o);
            ss += __shfl_xor_sync(0xffffffffu, ss, o);
        }
        if (lane == 0) {
            atomicAdd(&g_xraw[2 * b],     s);
            atomicAdd(&g_xraw[2 * b + 1], ss);
        }
    }
}

// =====================================================================
// final combine: out = x + b2 + sum of F2_SPLIT partials   (32 x 1024)
// =====================================================================
__global__ void final_kernel(const float* __restrict__ b2,
                             float* __restrict__ out)
{
    const int t  = blockIdx.x * blockDim.x + threadIdx.x;   // 0..8191 float4s
    const int m  = t >> 8;
    const int j4 = t & 255;
    float4 s = reinterpret_cast<const float4*>(g_x)[t];
    const float4 bb = reinterpret_cast<const float4*>(b2)[j4];
    s.x += bb.x; s.y += bb.y; s.z += bb.z; s.w += bb.w;
    #pragma unroll
    for (int sp = 0; sp < F2_SPLIT; ++sp) {
        const float4 p = *reinterpret_cast<const float4*>(
            g_part + W2_OFF + (size_t)(sp * BATCH + m) * NTOK + j4 * 4);
        s.x += p.x; s.y += p.y; s.z += p.z; s.w += p.w;
    }
    reinterpret_cast<float4*>(out)[t] = s;
}

// =====================================================================
extern "C" void kernel_launch(void* const* d_in, const int* in_sizes, int n_in,
                              void* d_out, int out_size)
{
    const float* Q       = (const float*)d_in[0];
    const float* Kt      = (const float*)d_in[1];
    const float* Vt      = (const float*)d_in[2];
    const float* mu_w    = (const float*)d_in[3];
    const float* mu_b    = (const float*)d_in[4];
    const float* sigma_w = (const float*)d_in[5];
    const float* sigma_b = (const float*)d_in[6];
    const float* ffn_w1  = (const float*)d_in[7];
    const float* ffn_b1  = (const float*)d_in[8];
    const float* ffn_w2  = (const float*)d_in[9];
    const float* ffn_b2  = (const float*)d_in[10];
    const float* ln_ff_g = (const float*)d_in[11];
    const float* ln_ff_b = (const float*)d_in[12];
    const float* ln_q_g  = (const float*)d_in[13];
    const float* ln_q_b  = (const float*)d_in[14];
    float* out = (float*)d_out;

    cudaFuncSetAttribute(gemm_kernel<0, 8>,
                         cudaFuncAttributeMaxDynamicSharedMemorySize, GEMM_SMEM(8));
    cudaFuncSetAttribute(gemm_kernel<1, 16>,
                         cudaFuncAttributeMaxDynamicSharedMemorySize, GEMM_SMEM(16));
    cudaFuncSetAttribute(gemm_kernel<2, 16>,
                         cudaFuncAttributeMaxDynamicSharedMemorySize, GEMM_SMEM(16));

    // 1. Q row stats + zero x-stat accumulators
    stats_kernel<<<1, 1024>>>(Q);

    // 2. mu & sigma partial GEMMs on LN(Q), split-K 32 (K=32/block)
    //    -> 256 blocks, full chip
    gemm_kernel<0, 8><<<dim3(NTOK / 256, MS_SPLIT, 2), 256, GEMM_SMEM(8)>>>(
        mu_w, sigma_w, NTOK, NTOK, MU_OFF, SIG_OFF - MU_OFF,
        Q, ln_q_g, ln_q_b, nullptr);

    // 3. Gaussian stream + mu/sigma combine + x-stat atomics
    gauss_kernel<<<(BATCH * NTOK) / 8, 256>>>(Kt, Vt, Q, mu_b, sigma_b);

    // 4. FFN GEMM 1 on LN(g_x), split-K 16 (K=64/block) -> 256 blocks
    gemm_kernel<1, 16><<<dim3(MFF / 256, F1_SPLIT, 1), 256, GEMM_SMEM(16)>>>(
        ffn_w1, ffn_w1, NTOK, MFF, W1_OFF, 0,
        nullptr, ln_ff_g, ln_ff_b, nullptr);

    // 5. FFN GEMM 2 on silu(partials + b1), split-K 64 -> 256 blocks
    gemm_kernel<2, 16><<<dim3(NTOK / 256, F2_SPLIT, 1), 256, GEMM_SMEM(16)>>>(
        ffn_w2, ffn_w2, MFF, NTOK, W2_OFF, 0,
        nullptr, nullptr, nullptr, ffn_b1);

    // 6. out = x + b2 + sum of FFN2 partials
    final_kernel<<<64, 128>>>(ffn_b2, out);
}

// round 15
// speedup vs baseline: 1.0686x; 1.0102x over previous
#include <cuda_runtime.h>
#include <cstdint>

// ---------------- problem constants ----------------
#define BATCH   32
#define NTOK    1024
#define DDIM    1024
#define MFF     4096
#define LN_EPS  1e-5f

#define MS_SPLIT 16
#define F1_SPLIT 16
#define F2_SPLIT 64

// ---------------- scratch ----------------
__device__ float g_x    [BATCH * NTOK];
__device__ float g_qstat[64];                 // (mean, rstd) per Q row
__device__ float g_xraw [64];                 // (sum, sumsq) per x row (atomics)
__device__ float g_part [4194304];            // split-K partials (16 MB)

#define MU_OFF  0                             // 16*32*1024 = 524288
#define SIG_OFF 524288
#define W1_OFF  0                             // 16*32*4096 = 2097152 (reuses mu/sig)
#define W2_OFF  2097152                       // 64*32*1024 = 2097152

// dynamic smem: W [256 n][68] + A [32 m][68], both k-major
#define GEMM_SMEM ((256 * 68 + 32 * 68) * 4)  // 78336 B -> 2 blocks/SM

__device__ __forceinline__ uint32_t smem_u32(const void* p)
{
    return (uint32_t)__cvta_generic_to_shared(p);
}
#define CP_ASYNC16(dst, src) \
    asm volatile("cp.async.ca.shared.global [%0], [%1], 16;\n" \
                 :: "r"(dst), "l"(src))

// =====================================================================
// Q row stats (mean, rstd) + zero the x-stat accumulators. 1 block.
// =====================================================================
__global__ void stats_kernel(const float* __restrict__ Q)
{
    const int tid = threadIdx.x;
    if (tid < 64) g_xraw[tid] = 0.f;
    const int r = tid >> 5, lane = tid & 31;
    const float4* p = reinterpret_cast<const float4*>(Q + r * NTOK);
    float s = 0.f, ss = 0.f;
    #pragma unroll
    for (int i = 0; i < 8; ++i) {
        float4 v = p[lane + 32 * i];
        s  += v.x + v.y + v.z + v.w;
        ss += v.x*v.x + v.y*v.y + v.z*v.z + v.w*v.w;
    }
    #pragma unroll
    for (int o = 16; o; o >>= 1) {
        s  += __shfl_xor_sync(0xffffffffu, s,  o);
        ss += __shfl_xor_sync(0xffffffffu, ss, o);
    }
    if (lane == 0) {
        const float mean = s * (1.0f / NTOK);
        const float var  = ss * (1.0f / NTOK) - mean * mean;
        g_qstat[2 * r]     = mean;
        g_qstat[2 * r + 1] = rsqrtf(var + LN_EPS);
    }
}

// =====================================================================
// Split-K GEMM, k-pair-packed FFMA2 (round-10 design + 4-stage cp.async
// pipeline). Block tile 32(M) x 256(N); K strip 64; 256 threads; thread
// tile 8m x 4n (n strided by 64; rows padded to 68 floats = 17 x 16B,
// odd -> conflict-free LDS.128). W fetched in FOUR commit groups of 16 k
// each; compute of group g waits only on groups <= g, so later groups
// stream from DRAM while earlier groups compute. Inner loop per k-quad:
// 4 LDS.128 (W) + 8 broadcast LDS.128 (A) + 64 fma.f32x2 -> fma-bound.
// AMODE 0: A = LN(Q) (g_qstat)  1: A = LN(g_x) (g_xraw)
// AMODE 2: A = silu(sum of F1_SPLIT partials + b1)
// gridDim = (N/256, nsplit, nz); z selects W0/W1 (mu/sigma fusion).
// =====================================================================
template<int AMODE>
__global__ __launch_bounds__(256, 2)
void gemm_kernel(const float* __restrict__ W0, const float* __restrict__ W1,
                 int ldw, int N, int partOff, int partStrideZ,
                 const float* __restrict__ Ain,
                 const float* __restrict__ lng, const float* __restrict__ lnb,
                 const float* __restrict__ b1)
{
    extern __shared__ __align__(16) float smem[];
    float* w_s = smem;              // [256 n][68] k-major
    float* a_s = smem + 256 * 68;   // [32 m][68]  k-major

    const int tid = threadIdx.x;
    const float* __restrict__ W = (blockIdx.z == 0) ? W0 : W1;
    float* __restrict__ P = g_part + partOff + (size_t)blockIdx.z * partStrideZ;

    const int j0    = blockIdx.x * 256;
    const int split = blockIdx.y;
    const int kOff  = split * 64;

    // ---- async W fetch: 4 commit groups x 4 quads (16 k) each ----
    const uint32_t wbase = smem_u32(w_s);
    #pragma unroll
    for (int g = 0; g < 4; ++g) {
        #pragma unroll
        for (int j = 0; j < 4; ++j) {
            const int idx = j * 256 + tid;       // 0..1023
            const int n   = idx >> 2;            // 0..255
            const int kq  = (idx & 3) + 4 * g;   // quads of group g
            const float* src = W + (size_t)(j0 + n) * ldw + kOff + kq * 4;
            CP_ASYNC16(wbase + (uint32_t)((n * 68 + kq * 4) * 4), src);
        }
        asm volatile("cp.async.commit_group;\n");
    }

    // ---- A panel build (overlaps all 4 groups in flight) ----
    #pragma unroll
    for (int t = 0; t < 2; ++t) {
        const int idx = t * 256 + tid;
        const int ra  = idx >> 4;          // 0..31
        const int kq  = idx & 15;
        const int kc  = kOff + kq * 4;
        float4 av;
        if (AMODE < 2) {
            float mean, rs;
            if (AMODE == 0) { mean = g_qstat[2 * ra]; rs = g_qstat[2 * ra + 1]; }
            else {
                const float s  = g_xraw[2 * ra];
                const float ss = g_xraw[2 * ra + 1];
                mean = s * (1.0f / NTOK);
                rs   = rsqrtf(ss * (1.0f / NTOK) - mean * mean + LN_EPS);
            }
            const float* Arow = (AMODE == 1) ? (g_x + ra * NTOK) : (Ain + ra * NTOK);
            const float4 fa = *reinterpret_cast<const float4*>(Arow + kc);
            const float4 fg = *reinterpret_cast<const float4*>(lng + kc);
            const float4 fb = *reinterpret_cast<const float4*>(lnb + kc);
            av.x = (fa.x - mean) * rs * fg.x + fb.x;
            av.y = (fa.y - mean) * rs * fg.y + fb.y;
            av.z = (fa.z - mean) * rs * fg.z + fb.z;
            av.w = (fa.w - mean) * rs * fg.w + fb.w;
        } else {
            float4 v = *reinterpret_cast<const float4*>(b1 + kc);
            #pragma unroll
            for (int s = 0; s < F1_SPLIT; ++s) {
                const float4 p = *reinterpret_cast<const float4*>(
                    g_part + W1_OFF + (size_t)(s * BATCH + ra) * MFF + kc);
                v.x += p.x; v.y += p.y; v.z += p.z; v.w += p.w;
            }
            av.x = v.x / (1.0f + __expf(-v.x));
            av.y = v.y / (1.0f + __expf(-v.y));
            av.z = v.z / (1.0f + __expf(-v.z));
            av.w = v.w / (1.0f + __expf(-v.w));
        }
        *reinterpret_cast<float4*>(&a_s[ra * 68 + kq * 4]) = av;
    }

    // ---- compute: group g as soon as it lands; later groups stream ----
    const int tx = tid & 63, ty = tid >> 6;    // n: tx+64*ni, m: 8*ty+mi

    unsigned long long acc[8][4];
    #pragma unroll
    for (int mi = 0; mi < 8; ++mi)
        #pragma unroll
        for (int ni = 0; ni < 4; ++ni) acc[mi][ni] = 0ull;

    #pragma unroll
    for (int g = 0; g < 4; ++g) {
        if      (g == 0) asm volatile("cp.async.wait_group 3;\n");
        else if (g == 1) asm volatile("cp.async.wait_group 2;\n");
        else if (g == 2) asm volatile("cp.async.wait_group 1;\n");
        else             asm volatile("cp.async.wait_group 0;\n");
        __syncthreads();
        #pragma unroll
        for (int kq = 4 * g; kq < 4 * g + 4; ++kq) {
            ulonglong2 wv[4];
            #pragma unroll
            for (int ni = 0; ni < 4; ++ni)
                wv[ni] = *reinterpret_cast<const ulonglong2*>(
                    &w_s[(tx + 64 * ni) * 68 + kq * 4]);
            #pragma unroll
            for (int mi = 0; mi < 8; ++mi) {
                const ulonglong2 avv = *reinterpret_cast<const ulonglong2*>(
                    &a_s[(8 * ty + mi) * 68 + kq * 4]);
                #pragma unroll
                for (int ni = 0; ni < 4; ++ni) {
                    asm("fma.rn.f32x2 %0, %1, %2, %0;"
                        : "+l"(acc[mi][ni]) : "l"(avv.x), "l"(wv[ni].x));
                    asm("fma.rn.f32x2 %0, %1, %2, %0;"
                        : "+l"(acc[mi][ni]) : "l"(avv.y), "l"(wv[ni].y));
                }
            }
        }
    }

    // ---- epilogue: fold (even,odd); m = 8ty+mi, n = j0+tx+64ni ----
    #pragma unroll
    for (int mi = 0; mi < 8; ++mi) {
        float* dst = P + (size_t)(split * BATCH + 8 * ty + mi) * N + j0;
        #pragma unroll
        for (int ni = 0; ni < 4; ++ni) {
            float lo, hi;
            asm("mov.b64 {%0, %1}, %2;" : "=f"(lo), "=f"(hi) : "l"(acc[mi][ni]));
            dst[tx + 64 * ni] = lo + hi;
        }
    }
}

// =====================================================================
// Gaussian pseudo-attention: one warp per (b,i), streams K/V (256 MB)
// with all 16 row loads batched up front (MLP=16). Folds mu/sigma
// split-K combine; accumulates LN(x) stats via atomics.
// =====================================================================
__global__ __launch_bounds__(256)
void gauss_kernel(const float* __restrict__ Kp,
                  const float* __restrict__ Vp,
                  const float* __restrict__ Qp,
                  const float* __restrict__ mu_b,
                  const float* __restrict__ sig_b)
{
    const int tid  = threadIdx.x;
    const int w    = blockIdx.x * 8 + (tid >> 5);
    const int lane = tid & 31;
    const int b = w >> 10;
    const int i = w & 1023;

    float mu = mu_b[i];
    float sg = sig_b[i];
    #pragma unroll
    for (int s = 0; s < MS_SPLIT; ++s) {
        mu += g_part[MU_OFF  + (s * BATCH + b) * NTOK + i];
        sg += g_part[SIG_OFF + (s * BATCH + b) * NTOK + i];
    }
    mu = tanhf(mu);
    const float coef = -0.5f / (sg * sg + 1e-8f);

    const float4* K4 = reinterpret_cast<const float4*>(Kp) + (size_t)w * (DDIM / 4);
    const float4* V4 = reinterpret_cast<const float4*>(Vp) + (size_t)w * (DDIM / 4);

    float4 kr[8], vr[8];
    #pragma unroll
    for (int it = 0; it < 8; ++it) kr[it] = __ldcs(&K4[it * 32 + lane]);
    #pragma unroll
    for (int it = 0; it < 8; ++it) vr[it] = __ldcs(&V4[it * 32 + lane]);

    float acc = 0.f;
    #pragma unroll
    for (int it = 0; it < 8; ++it) {
        float d;
        d = kr[it].x - mu; acc += __expf(coef * d * d) * vr[it].x;
        d = kr[it].y - mu; acc += __expf(coef * d * d) * vr[it].y;
        d = kr[it].z - mu; acc += __expf(coef * d * d) * vr[it].z;
        d = kr[it].w - mu; acc += __expf(coef * d * d) * vr[it].w;
    }
    #pragma unroll
    for (int o = 16; o; o >>= 1) acc += __shfl_xor_sync(0xffffffffu, acc, o);

    __shared__ float shv[8];
    if (lane == 0) {
        const float v = acc + Qp[w];
        g_x[w] = v;
        shv[tid >> 5] = v;
    }
    __syncthreads();
    if (tid < 32) {
        float v = (lane < 8) ? shv[lane] : 0.f;
        float s = v, ss = v * v;
        #pragma unroll
        for (int o = 4; o; o >>= 1) {
            s  += __shfl_xor_sync(0xffffffffu, s,  o);
            ss += __shfl_xor_sync(0xffffffffu, ss, o);
        }
        if (lane == 0) {
            atomicAdd(&g_xraw[2 * b],     s);
            atomicAdd(&g_xraw[2 * b + 1], ss);
        }
    }
}

// =====================================================================
// final combine: out = x + b2 + sum of F2_SPLIT partials   (32 x 1024)
// =====================================================================
__global__ void final_kernel(const float* __restrict__ b2,
                             float* __restrict__ out)
{
    const int t  = blockIdx.x * blockDim.x + threadIdx.x;   // 0..8191 float4s
    const int m  = t >> 8;
    const int j4 = t & 255;
    float4 s = reinterpret_cast<const float4*>(g_x)[t];
    const float4 bb = reinterpret_cast<const float4*>(b2)[j4];
    s.x += bb.x; s.y += bb.y; s.z += bb.z; s.w += bb.w;
    #pragma unroll
    for (int sp = 0; sp < F2_SPLIT; ++sp) {
        const float4 p = *reinterpret_cast<const float4*>(
            g_part + W2_OFF + (size_t)(sp * BATCH + m) * NTOK + j4 * 4);
        s.x += p.x; s.y += p.y; s.z += p.z; s.w += p.w;
    }
    reinterpret_cast<float4*>(out)[t] = s;
}

// =====================================================================
extern "C" void kernel_launch(void* const* d_in, const int* in_sizes, int n_in,
                              void* d_out, int out_size)
{
    const float* Q       = (const float*)d_in[0];
    const float* Kt      = (const float*)d_in[1];
    const float* Vt      = (const float*)d_in[2];
    const float* mu_w    = (const float*)d_in[3];
    const float* mu_b    = (const float*)d_in[4];
    const float* sigma_w = (const float*)d_in[5];
    const float* sigma_b = (const float*)d_in[6];
    const float* ffn_w1  = (const float*)d_in[7];
    const float* ffn_b1  = (const float*)d_in[8];
    const float* ffn_w2  = (const float*)d_in[9];
    const float* ffn_b2  = (const float*)d_in[10];
    const float* ln_ff_g = (const float*)d_in[11];
    const float* ln_ff_b = (const float*)d_in[12];
    const float* ln_q_g  = (const float*)d_in[13];
    const float* ln_q_b  = (const float*)d_in[14];
    float* out = (float*)d_out;

    cudaFuncSetAttribute(gemm_kernel<0>,
                         cudaFuncAttributeMaxDynamicSharedMemorySize, GEMM_SMEM);
    cudaFuncSetAttribute(gemm_kernel<1>,
                         cudaFuncAttributeMaxDynamicSharedMemorySize, GEMM_SMEM);
    cudaFuncSetAttribute(gemm_kernel<2>,
                         cudaFuncAttributeMaxDynamicSharedMemorySize, GEMM_SMEM);

    // 1. Q row stats + zero x-stat accumulators
    stats_kernel<<<1, 1024>>>(Q);

    // 2. mu & sigma partial GEMMs on LN(Q), split-K 16, z selects matrix
    gemm_kernel<0><<<dim3(NTOK / 256, MS_SPLIT, 2), 256, GEMM_SMEM>>>(
        mu_w, sigma_w, NTOK, NTOK, MU_OFF, SIG_OFF - MU_OFF,
        Q, ln_q_g, ln_q_b, nullptr);

    // 3. Gaussian stream + mu/sigma combine + x-stat atomics
    gauss_kernel<<<(BATCH * NTOK) / 8, 256>>>(Kt, Vt, Q, mu_b, sigma_b);

    // 4. FFN GEMM 1 on LN(g_x), split-K 16 -> 256 blocks
    gemm_kernel<1><<<dim3(MFF / 256, F1_SPLIT, 1), 256, GEMM_SMEM>>>(
        ffn_w1, ffn_w1, NTOK, MFF, W1_OFF, 0,
        nullptr, ln_ff_g, ln_ff_b, nullptr);

    // 5. FFN GEMM 2 on silu(partials + b1), split-K 64 -> 256 blocks
    gemm_kernel<2><<<dim3(NTOK / 256, F2_SPLIT, 1), 256, GEMM_SMEM>>>(
        ffn_w2, ffn_w2, MFF, NTOK, W2_OFF, 0,
        nullptr, nullptr, nullptr, ffn_b1);

    // 6. out = x + b2 + sum of FFN2 partials
    final_kernel<<<64, 128>>>(ffn_b2, out);
}

// round 16
// speedup vs baseline: 1.1601x; 1.0856x over previous
#include <cuda_runtime.h>
#include <cstdint>

// ---------------- problem constants ----------------
#define BATCH   32
#define NTOK    1024
#define DDIM    1024
#define MFF     4096
#define LN_EPS  1e-5f

#define MS_SPLIT 16
#define F1_SPLIT 16
#define F2_SPLIT 64

// ---------------- scratch ----------------
__device__ float g_x    [BATCH * NTOK];
__device__ float g_qstat[64];                 // (mean, rstd) per Q row
__device__ float g_xraw [64];                 // (sum, sumsq) per x row (atomics)
__device__ float g_part [4194304];            // split-K partials (16 MB)

#define MU_OFF  0                             // 16*32*1024 = 524288
#define SIG_OFF 524288
#define W1_OFF  0                             // 16*32*4096 = 2097152 (reuses mu/sig)
#define W2_OFF  2097152                       // 64*32*1024 = 2097152

// dynamic smem: W [256 n][68] + A [32 m][68], both k-major
#define GEMM_SMEM ((256 * 68 + 32 * 68) * 4)  // 78336 B -> 2 blocks/SM

__device__ __forceinline__ uint32_t smem_u32(const void* p)
{
    return (uint32_t)__cvta_generic_to_shared(p);
}
#define CP_ASYNC16(dst, src) \
    asm volatile("cp.async.ca.shared.global [%0], [%1], 16;\n" \
                 :: "r"(dst), "l"(src))

__device__ __forceinline__ uint32_t f2tf32(float x)
{
    uint32_t r;
    asm("cvt.rna.tf32.f32 %0, %1;" : "=r"(r) : "f"(x));
    return r;
}
#define MMA_TF32(c, a, b0, b1) \
    asm volatile("mma.sync.aligned.m16n8k8.row.col.f32.tf32.tf32.f32 " \
        "{%0,%1,%2,%3}, {%4,%5,%6,%7}, {%8,%9}, {%0,%1,%2,%3};" \
        : "+f"((c)[0]), "+f"((c)[1]), "+f"((c)[2]), "+f"((c)[3]) \
        : "r"((a)[0]), "r"((a)[1]), "r"((a)[2]), "r"((a)[3]), \
          "r"(b0), "r"(b1))

// =====================================================================
// Q row stats (mean, rstd) + zero the x-stat accumulators. 1 block.
// =====================================================================
__global__ void stats_kernel(const float* __restrict__ Q)
{
    const int tid = threadIdx.x;
    if (tid < 64) g_xraw[tid] = 0.f;
    const int r = tid >> 5, lane = tid & 31;
    const float4* p = reinterpret_cast<const float4*>(Q + r * NTOK);
    float s = 0.f, ss = 0.f;
    #pragma unroll
    for (int i = 0; i < 8; ++i) {
        float4 v = p[lane + 32 * i];
        s  += v.x + v.y + v.z + v.w;
        ss += v.x*v.x + v.y*v.y + v.z*v.z + v.w*v.w;
    }
    #pragma unroll
    for (int o = 16; o; o >>= 1) {
        s  += __shfl_xor_sync(0xffffffffu, s,  o);
        ss += __shfl_xor_sync(0xffffffffu, ss, o);
    }
    if (lane == 0) {
        const float mean = s * (1.0f / NTOK);
        const float var  = ss * (1.0f / NTOK) - mean * mean;
        g_qstat[2 * r]     = mean;
        g_qstat[2 * r + 1] = rsqrtf(var + LN_EPS);
    }
}

// =====================================================================
// Shared loader: W strip via 4 cp.async commit groups (16 k each) and
// A panel (LN or silu-combine applied) into k-major smem panels.
// =====================================================================
template<int AMODE>
__device__ __forceinline__ void load_panels(
    float* w_s, float* a_s, const float* __restrict__ W, int ldw,
    int j0, int kOff, int tid,
    const float* __restrict__ Ain,
    const float* __restrict__ lng, const float* __restrict__ lnb,
    const float* __restrict__ b1)
{
    const uint32_t wbase = smem_u32(w_s);
    #pragma unroll
    for (int g = 0; g < 4; ++g) {
        #pragma unroll
        for (int j = 0; j < 4; ++j) {
            const int idx = j * 256 + tid;       // 0..1023
            const int n   = idx >> 2;            // 0..255
            const int kq  = (idx & 3) + 4 * g;   // quads of group g
            const float* src = W + (size_t)(j0 + n) * ldw + kOff + kq * 4;
            CP_ASYNC16(wbase + (uint32_t)((n * 68 + kq * 4) * 4), src);
        }
        asm volatile("cp.async.commit_group;\n");
    }

    #pragma unroll
    for (int t = 0; t < 2; ++t) {
        const int idx = t * 256 + tid;
        const int ra  = idx >> 4;          // 0..31
        const int kq  = idx & 15;
        const int kc  = kOff + kq * 4;
        float4 av;
        if (AMODE < 2) {
            float mean, rs;
            if (AMODE == 0) { mean = g_qstat[2 * ra]; rs = g_qstat[2 * ra + 1]; }
            else {
                const float s  = g_xraw[2 * ra];
                const float ss = g_xraw[2 * ra + 1];
                mean = s * (1.0f / NTOK);
                rs   = rsqrtf(ss * (1.0f / NTOK) - mean * mean + LN_EPS);
            }
            const float* Arow = (AMODE == 1) ? (g_x + ra * NTOK) : (Ain + ra * NTOK);
            const float4 fa = *reinterpret_cast<const float4*>(Arow + kc);
            const float4 fg = *reinterpret_cast<const float4*>(lng + kc);
            const float4 fb = *reinterpret_cast<const float4*>(lnb + kc);
            av.x = (fa.x - mean) * rs * fg.x + fb.x;
            av.y = (fa.y - mean) * rs * fg.y + fb.y;
            av.z = (fa.z - mean) * rs * fg.z + fb.z;
            av.w = (fa.w - mean) * rs * fg.w + fb.w;
        } else {
            float4 v = *reinterpret_cast<const float4*>(b1 + kc);
            #pragma unroll
            for (int s = 0; s < F1_SPLIT; ++s) {
                const float4 p = *reinterpret_cast<const float4*>(
                    g_part + W1_OFF + (size_t)(s * BATCH + ra) * MFF + kc);
                v.x += p.x; v.y += p.y; v.z += p.z; v.w += p.w;
            }
            av.x = v.x / (1.0f + __expf(-v.x));
            av.y = v.y / (1.0f + __expf(-v.y));
            av.z = v.z / (1.0f + __expf(-v.z));
            av.w = v.w / (1.0f + __expf(-v.w));
        }
        *reinterpret_cast<float4*>(&a_s[ra * 68 + kq * 4]) = av;
    }
}

// =====================================================================
// FFMA split-K GEMM (exact fp32) — used for mu/sigma only (precision).
// Round-10/15 design: 32x256 tile, K strip 64, k-pair-packed FFMA2.
// =====================================================================
template<int AMODE>
__global__ __launch_bounds__(256, 2)
void gemm_kernel(const float* __restrict__ W0, const float* __restrict__ W1,
                 int ldw, int N, int partOff, int partStrideZ,
                 const float* __restrict__ Ain,
                 const float* __restrict__ lng, const float* __restrict__ lnb,
                 const float* __restrict__ b1)
{
    extern __shared__ __align__(16) float smem[];
    float* w_s = smem;              // [256 n][68] k-major
    float* a_s = smem + 256 * 68;   // [32 m][68]  k-major

    const int tid = threadIdx.x;
    const float* __restrict__ W = (blockIdx.z == 0) ? W0 : W1;
    float* __restrict__ P = g_part + partOff + (size_t)blockIdx.z * partStrideZ;

    const int j0    = blockIdx.x * 256;
    const int split = blockIdx.y;
    const int kOff  = split * 64;

    load_panels<AMODE>(w_s, a_s, W, ldw, j0, kOff, tid, Ain, lng, lnb, b1);

    const int tx = tid & 63, ty = tid >> 6;

    unsigned long long acc[8][4];
    #pragma unroll
    for (int mi = 0; mi < 8; ++mi)
        #pragma unroll
        for (int ni = 0; ni < 4; ++ni) acc[mi][ni] = 0ull;

    #pragma unroll
    for (int g = 0; g < 4; ++g) {
        if      (g == 0) asm volatile("cp.async.wait_group 3;\n");
        else if (g == 1) asm volatile("cp.async.wait_group 2;\n");
        else if (g == 2) asm volatile("cp.async.wait_group 1;\n");
        else             asm volatile("cp.async.wait_group 0;\n");
        __syncthreads();
        #pragma unroll
        for (int kq = 4 * g; kq < 4 * g + 4; ++kq) {
            ulonglong2 wv[4];
            #pragma unroll
            for (int ni = 0; ni < 4; ++ni)
                wv[ni] = *reinterpret_cast<const ulonglong2*>(
                    &w_s[(tx + 64 * ni) * 68 + kq * 4]);
            #pragma unroll
            for (int mi = 0; mi < 8; ++mi) {
                const ulonglong2 avv = *reinterpret_cast<const ulonglong2*>(
                    &a_s[(8 * ty + mi) * 68 + kq * 4]);
                #pragma unroll
                for (int ni = 0; ni < 4; ++ni) {
                    asm("fma.rn.f32x2 %0, %1, %2, %0;"
                        : "+l"(acc[mi][ni]) : "l"(avv.x), "l"(wv[ni].x));
                    asm("fma.rn.f32x2 %0, %1, %2, %0;"
                        : "+l"(acc[mi][ni]) : "l"(avv.y), "l"(wv[ni].y));
                }
            }
        }
    }

    #pragma unroll
    for (int mi = 0; mi < 8; ++mi) {
        float* dst = P + (size_t)(split * BATCH + 8 * ty + mi) * N + j0;
        #pragma unroll
        for (int ni = 0; ni < 4; ++ni) {
            float lo, hi;
            asm("mov.b64 {%0, %1}, %2;" : "=f"(lo), "=f"(hi) : "l"(acc[mi][ni]));
            dst[tx + 64 * ni] = lo + hi;
        }
    }
}

// =====================================================================
// tf32 tensor-core split-K GEMM — FFN1 / FFN2.
// Same tile/loader; compute via mma.sync.m16n8k8.tf32 (fp32 accum).
// Warp w owns n-range [32w, 32w+32): 4 n-tiles x 2 m-tiles = 8 mma per
// k8 step. Fragment loads from the k-major panels are conflict-free
// (68-float rows: bank = 4*grp + tig, all 32 distinct).
// =====================================================================
template<int AMODE>
__global__ __launch_bounds__(256, 2)
void gemm_tc_kernel(const float* __restrict__ W0,
                    int ldw, int N, int partOff,
                    const float* __restrict__ lng, const float* __restrict__ lnb,
                    const float* __restrict__ b1)
{
    extern __shared__ __align__(16) float smem[];
    float* w_s = smem;              // [256 n][68] k-major
    float* a_s = smem + 256 * 68;   // [32 m][68]  k-major

    const int tid = threadIdx.x;
    float* __restrict__ P = g_part + partOff;

    const int j0    = blockIdx.x * 256;
    const int split = blockIdx.y;
    const int kOff  = split * 64;

    load_panels<AMODE>(w_s, a_s, W0, ldw, j0, kOff, tid, nullptr, lng, lnb, b1);

    const int lane = tid & 31;
    const int wid  = tid >> 5;      // n block: 32*wid
    const int grp  = lane >> 2;     // 0..7
    const int tig  = lane & 3;      // 0..3

    float c[2][4][4];
    #pragma unroll
    for (int mt = 0; mt < 2; ++mt)
        #pragma unroll
        for (int nt = 0; nt < 4; ++nt)
            #pragma unroll
            for (int j = 0; j < 4; ++j) c[mt][nt][j] = 0.f;

    #pragma unroll
    for (int g = 0; g < 4; ++g) {
        if      (g == 0) asm volatile("cp.async.wait_group 3;\n");
        else if (g == 1) asm volatile("cp.async.wait_group 2;\n");
        else if (g == 2) asm volatile("cp.async.wait_group 1;\n");
        else             asm volatile("cp.async.wait_group 0;\n");
        __syncthreads();
        #pragma unroll
        for (int s2 = 0; s2 < 2; ++s2) {
            const int k0 = g * 16 + s2 * 8;
            uint32_t a[2][4];
            #pragma unroll
            for (int mt = 0; mt < 2; ++mt) {
                const float* ar0 = a_s + (mt * 16 + grp) * 68 + k0 + tig;
                const float* ar1 = ar0 + 8 * 68;
                a[mt][0] = f2tf32(ar0[0]);
                a[mt][1] = f2tf32(ar1[0]);
                a[mt][2] = f2tf32(ar0[4]);
                a[mt][3] = f2tf32(ar1[4]);
            }
            #pragma unroll
            for (int nt = 0; nt < 4; ++nt) {
                const float* br = w_s + (wid * 32 + nt * 8 + grp) * 68 + k0 + tig;
                const uint32_t b0 = f2tf32(br[0]);
                const uint32_t b1v = f2tf32(br[4]);
                MMA_TF32(c[0][nt], a[0], b0, b1v);
                MMA_TF32(c[1][nt], a[1], b0, b1v);
            }
        }
    }

    // epilogue: rows mt*16+grp (+8), cols j0+32wid+8nt+2tig (+1)
    #pragma unroll
    for (int mt = 0; mt < 2; ++mt) {
        const int m0 = split * BATCH + mt * 16 + grp;
        #pragma unroll
        for (int nt = 0; nt < 4; ++nt) {
            float* d0 = P + (size_t)m0 * N + j0 + wid * 32 + nt * 8 + 2 * tig;
            float* d1 = d0 + (size_t)8 * N;
            *reinterpret_cast<float2*>(d0) = make_float2(c[mt][nt][0], c[mt][nt][1]);
            *reinterpret_cast<float2*>(d1) = make_float2(c[mt][nt][2], c[mt][nt][3]);
        }
    }
}

// =====================================================================
// Gaussian pseudo-attention: one warp per (b,i), streams K/V (256 MB)
// with all 16 row loads batched up front (MLP=16). Folds mu/sigma
// split-K combine; accumulates LN(x) stats via atomics.
// =====================================================================
__global__ __launch_bounds__(256)
void gauss_kernel(const float* __restrict__ Kp,
                  const float* __restrict__ Vp,
                  const float* __restrict__ Qp,
                  const float* __restrict__ mu_b,
                  const float* __restrict__ sig_b)
{
    const int tid  = threadIdx.x;
    const int w    = blockIdx.x * 8 + (tid >> 5);
    const int lane = tid & 31;
    const int b = w >> 10;
    const int i = w & 1023;

    float mu = mu_b[i];
    float sg = sig_b[i];
    #pragma unroll
    for (int s = 0; s < MS_SPLIT; ++s) {
        mu += g_part[MU_OFF  + (s * BATCH + b) * NTOK + i];
        sg += g_part[SIG_OFF + (s * BATCH + b) * NTOK + i];
    }
    mu = tanhf(mu);
    const float coef = -0.5f / (sg * sg + 1e-8f);

    const float4* K4 = reinterpret_cast<const float4*>(Kp) + (size_t)w * (DDIM / 4);
    const float4* V4 = reinterpret_cast<const float4*>(Vp) + (size_t)w * (DDIM / 4);

    float4 kr[8], vr[8];
    #pragma unroll
    for (int it = 0; it < 8; ++it) kr[it] = __ldcs(&K4[it * 32 + lane]);
    #pragma unroll
    for (int it = 0; it < 8; ++it) vr[it] = __ldcs(&V4[it * 32 + lane]);

    float acc = 0.f;
    #pragma unroll
    for (int it = 0; it < 8; ++it) {
        float d;
        d = kr[it].x - mu; acc += __expf(coef * d * d) * vr[it].x;
        d = kr[it].y - mu; acc += __expf(coef * d * d) * vr[it].y;
        d = kr[it].z - mu; acc += __expf(coef * d * d) * vr[it].z;
        d = kr[it].w - mu; acc += __expf(coef * d * d) * vr[it].w;
    }
    #pragma unroll
    for (int o = 16; o; o >>= 1) acc += __shfl_xor_sync(0xffffffffu, acc, o);

    __shared__ float shv[8];
    if (lane == 0) {
        const float v = acc + Qp[w];
        g_x[w] = v;
        shv[tid >> 5] = v;
    }
    __syncthreads();
    if (tid < 32) {
        float v = (lane < 8) ? shv[lane] : 0.f;
        float s = v, ss = v * v;
        #pragma unroll
        for (int o = 4; o; o >>= 1) {
            s  += __shfl_xor_sync(0xffffffffu, s,  o);
            ss += __shfl_xor_sync(0xffffffffu, ss, o);
        }
        if (lane == 0) {
            atomicAdd(&g_xraw[2 * b],     s);
            atomicAdd(&g_xraw[2 * b + 1], ss);
        }
    }
}

// =====================================================================
// final combine: out = x + b2 + sum of F2_SPLIT partials   (32 x 1024)
// =====================================================================
__global__ void final_kernel(const float* __restrict__ b2,
                             float* __restrict__ out)
{
    const int t  = blockIdx.x * blockDim.x + threadIdx.x;   // 0..8191 float4s
    const int m  = t >> 8;
    const int j4 = t & 255;
    float4 s = reinterpret_cast<const float4*>(g_x)[t];
    const float4 bb = reinterpret_cast<const float4*>(b2)[j4];
    s.x += bb.x; s.y += bb.y; s.z += bb.z; s.w += bb.w;
    #pragma unroll
    for (int sp = 0; sp < F2_SPLIT; ++sp) {
        const float4 p = *reinterpret_cast<const float4*>(
            g_part + W2_OFF + (size_t)(sp * BATCH + m) * NTOK + j4 * 4);
        s.x += p.x; s.y += p.y; s.z += p.z; s.w += p.w;
    }
    reinterpret_cast<float4*>(out)[t] = s;
}

// =====================================================================
extern "C" void kernel_launch(void* const* d_in, const int* in_sizes, int n_in,
                              void* d_out, int out_size)
{
    const float* Q       = (const float*)d_in[0];
    const float* Kt      = (const float*)d_in[1];
    const float* Vt      = (const float*)d_in[2];
    const float* mu_w    = (const float*)d_in[3];
    const float* mu_b    = (const float*)d_in[4];
    const float* sigma_w = (const float*)d_in[5];
    const float* sigma_b = (const float*)d_in[6];
    const float* ffn_w1  = (const float*)d_in[7];
    const float* ffn_b1  = (const float*)d_in[8];
    const float* ffn_w2  = (const float*)d_in[9];
    const float* ffn_b2  = (const float*)d_in[10];
    const float* ln_ff_g = (const float*)d_in[11];
    const float* ln_ff_b = (const float*)d_in[12];
    const float* ln_q_g  = (const float*)d_in[13];
    const float* ln_q_b  = (const float*)d_in[14];
    float* out = (float*)d_out;

    cudaFuncSetAttribute(gemm_kernel<0>,
                         cudaFuncAttributeMaxDynamicSharedMemorySize, GEMM_SMEM);
    cudaFuncSetAttribute(gemm_tc_kernel<1>,
                         cudaFuncAttributeMaxDynamicSharedMemorySize, GEMM_SMEM);
    cudaFuncSetAttribute(gemm_tc_kernel<2>,
                         cudaFuncAttributeMaxDynamicSharedMemorySize, GEMM_SMEM);

    // 1. Q row stats + zero x-stat accumulators
    stats_kernel<<<1, 1024>>>(Q);

    // 2. mu & sigma partial GEMMs on LN(Q) — exact fp32 FFMA (precision)
    gemm_kernel<0><<<dim3(NTOK / 256, MS_SPLIT, 2), 256, GEMM_SMEM>>>(
        mu_w, sigma_w, NTOK, NTOK, MU_OFF, SIG_OFF - MU_OFF,
        Q, ln_q_g, ln_q_b, nullptr);

    // 3. Gaussian stream + mu/sigma combine + x-stat atomics
    gauss_kernel<<<(BATCH * NTOK) / 8, 256>>>(Kt, Vt, Q, mu_b, sigma_b);

    // 4. FFN GEMM 1 on LN(g_x), tf32 tensor cores, split-K 16
    gemm_tc_kernel<1><<<dim3(MFF / 256, F1_SPLIT), 256, GEMM_SMEM>>>(
        ffn_w1, NTOK, MFF, W1_OFF, ln_ff_g, ln_ff_b, nullptr);

    // 5. FFN GEMM 2 on silu(partials + b1), tf32 tensor cores, split-K 64
    gemm_tc_kernel<2><<<dim3(NTOK / 256, F2_SPLIT), 256, GEMM_SMEM>>>(
        ffn_w2, MFF, NTOK, W2_OFF, nullptr, nullptr, ffn_b1);

    // 6. out = x + b2 + sum of FFN2 partials
    final_kernel<<<64, 128>>>(ffn_b2, out);
}

// round 17
// speedup vs baseline: 1.1934x; 1.0287x over previous
#include <cuda_runtime.h>
#include <cstdint>

// ---------------- problem constants ----------------
#define BATCH   32
#define NTOK    1024
#define DDIM    1024
#define MFF     4096
#define LN_EPS  1e-5f

#define MS_SPLIT 16
#define F1_SPLIT 16
#define F2_SPLIT 64

// ---------------- scratch ----------------
__device__ float g_x    [BATCH * NTOK];
__device__ float g_qstat[64];                 // (mean, rstd) per Q row
__device__ float g_xraw [64];                 // (sum, sumsq) per x row (atomics)
__device__ float g_part [4194304];            // split-K partials (16 MB)

#define MU_OFF  0                             // 16*32*1024 = 524288
#define SIG_OFF 524288
#define W1_OFF  0                             // 16*32*4096 = 2097152 (reuses mu/sig)
#define W2_OFF  2097152                       // 64*32*1024 = 2097152

// dynamic smem: W [NBLK n][68] + A [32 m][68], both k-major
#define GEMM_SMEM(NBLK) (((NBLK) + 32) * 68 * 4)

__device__ __forceinline__ uint32_t smem_u32(const void* p)
{
    return (uint32_t)__cvta_generic_to_shared(p);
}
#define CP_ASYNC16(dst, src) \
    asm volatile("cp.async.ca.shared.global [%0], [%1], 16;\n" \
                 :: "r"(dst), "l"(src))

__device__ __forceinline__ uint32_t f2tf32(float x)
{
    uint32_t r;
    asm("cvt.rna.tf32.f32 %0, %1;" : "=r"(r) : "f"(x));
    return r;
}
#define MMA_TF32(c, a0, a1, a2, a3, b0, b1) \
    asm volatile("mma.sync.aligned.m16n8k8.row.col.f32.tf32.tf32.f32 " \
        "{%0,%1,%2,%3}, {%4,%5,%6,%7}, {%8,%9}, {%0,%1,%2,%3};" \
        : "+f"((c)[0]), "+f"((c)[1]), "+f"((c)[2]), "+f"((c)[3]) \
        : "r"(a0), "r"(a1), "r"(a2), "r"(a3), "r"(b0), "r"(b1))

// =====================================================================
// Q row stats (mean, rstd) + zero the x-stat accumulators. 1 block.
// =====================================================================
__global__ void stats_kernel(const float* __restrict__ Q)
{
    const int tid = threadIdx.x;
    if (tid < 64) g_xraw[tid] = 0.f;
    const int r = tid >> 5, lane = tid & 31;
    const float4* p = reinterpret_cast<const float4*>(Q + r * NTOK);
    float s = 0.f, ss = 0.f;
    #pragma unroll
    for (int i = 0; i < 8; ++i) {
        float4 v = p[lane + 32 * i];
        s  += v.x + v.y + v.z + v.w;
        ss += v.x*v.x + v.y*v.y + v.z*v.z + v.w*v.w;
    }
    #pragma unroll
    for (int o = 16; o; o >>= 1) {
        s  += __shfl_xor_sync(0xffffffffu, s,  o);
        ss += __shfl_xor_sync(0xffffffffu, ss, o);
    }
    if (lane == 0) {
        const float mean = s * (1.0f / NTOK);
        const float var  = ss * (1.0f / NTOK) - mean * mean;
        g_qstat[2 * r]     = mean;
        g_qstat[2 * r + 1] = rsqrtf(var + LN_EPS);
    }
}

// =====================================================================
// Loader: W strip (NBLK rows x 64 k) via 4 cp.async commit groups of
// 16 k each; A panel (LN or silu-combine applied) into k-major smem.
// =====================================================================
template<int AMODE, int NBLK>
__device__ __forceinline__ void load_panels(
    float* w_s, float* a_s, const float* __restrict__ W, int ldw,
    int j0, int kOff, int tid,
    const float* __restrict__ Ain,
    const float* __restrict__ lng, const float* __restrict__ lnb,
    const float* __restrict__ b1)
{
    const uint32_t wbase = smem_u32(w_s);
    #pragma unroll
    for (int g = 0; g < 4; ++g) {
        #pragma unroll
        for (int j = 0; j < NBLK / 64; ++j) {
            const int idx = j * 256 + tid;       // 0 .. NBLK*4-1
            const int n   = idx >> 2;            // 0..NBLK-1
            const int kq  = (idx & 3) + 4 * g;   // quads of group g
            const float* src = W + (size_t)(j0 + n) * ldw + kOff + kq * 4;
            CP_ASYNC16(wbase + (uint32_t)((n * 68 + kq * 4) * 4), src);
        }
        asm volatile("cp.async.commit_group;\n");
    }

    #pragma unroll
    for (int t = 0; t < 2; ++t) {
        const int idx = t * 256 + tid;
        const int ra  = idx >> 4;          // 0..31
        const int kq  = idx & 15;
        const int kc  = kOff + kq * 4;
        float4 av;
        if (AMODE < 2) {
            float mean, rs;
            if (AMODE == 0) { mean = g_qstat[2 * ra]; rs = g_qstat[2 * ra + 1]; }
            else {
                const float s  = g_xraw[2 * ra];
                const float ss = g_xraw[2 * ra + 1];
                mean = s * (1.0f / NTOK);
                rs   = rsqrtf(ss * (1.0f / NTOK) - mean * mean + LN_EPS);
            }
            const float* Arow = (AMODE == 1) ? (g_x + ra * NTOK) : (Ain + ra * NTOK);
            const float4 fa = *reinterpret_cast<const float4*>(Arow + kc);
            const float4 fg = *reinterpret_cast<const float4*>(lng + kc);
            const float4 fb = *reinterpret_cast<const float4*>(lnb + kc);
            av.x = (fa.x - mean) * rs * fg.x + fb.x;
            av.y = (fa.y - mean) * rs * fg.y + fb.y;
            av.z = (fa.z - mean) * rs * fg.z + fb.z;
            av.w = (fa.w - mean) * rs * fg.w + fb.w;
        } else {
            float4 v = *reinterpret_cast<const float4*>(b1 + kc);
            #pragma unroll
            for (int s = 0; s < F1_SPLIT; ++s) {
                const float4 p = *reinterpret_cast<const float4*>(
                    g_part + W1_OFF + (size_t)(s * BATCH + ra) * MFF + kc);
                v.x += p.x; v.y += p.y; v.z += p.z; v.w += p.w;
            }
            av.x = v.x / (1.0f + __expf(-v.x));
            av.y = v.y / (1.0f + __expf(-v.y));
            av.z = v.z / (1.0f + __expf(-v.z));
            av.w = v.w / (1.0f + __expf(-v.w));
        }
        *reinterpret_cast<float4*>(&a_s[ra * 68 + kq * 4]) = av;
    }
}

// =====================================================================
// tf32 tensor-core split-K GEMM. Block tile 32(M) x NBLK(N), K strip 64.
// PREC==1: plain tf32 (FFN path, error ~5e-4 on h, diluted by |x|>>|h|).
// PREC==3: 3xTF32 error compensation (mu/sigma path):
//          a*w ~= ah*wh + al*wh + ah*wl, ah=tf32(a), al=tf32(a-ah)
//          -> per-product error ~2^-22, near-fp32.
// Warp w owns NBLK/8 n-columns: NT = NBLK/64 n-tiles x 2 m-tiles per k8.
// Fragment loads from the k-major panels are conflict-free (68-float
// rows: bank = 4*grp + tig, all 32 distinct).
// gridDim = (N/NBLK, nsplit, nz); z selects W0/W1 (mu/sigma fusion).
// =====================================================================
template<int AMODE, int NBLK, int PREC>
__global__ __launch_bounds__(256, 2)
void gemm_tc_kernel(const float* __restrict__ W0, const float* __restrict__ W1,
                    int ldw, int N, int partOff, int partStrideZ,
                    const float* __restrict__ Ain,
                    const float* __restrict__ lng, const float* __restrict__ lnb,
                    const float* __restrict__ b1)
{
    constexpr int NT = NBLK / 64;   // n-tiles per warp

    extern __shared__ __align__(16) float smem[];
    float* w_s = smem;               // [NBLK n][68] k-major
    float* a_s = smem + NBLK * 68;   // [32 m][68]  k-major

    const int tid = threadIdx.x;
    const float* __restrict__ W = (blockIdx.z == 0) ? W0 : W1;
    float* __restrict__ P = g_part + partOff + (size_t)blockIdx.z * partStrideZ;

    const int j0    = blockIdx.x * NBLK;
    const int split = blockIdx.y;
    const int kOff  = split * 64;

    load_panels<AMODE, NBLK>(w_s, a_s, W, ldw, j0, kOff, tid, Ain, lng, lnb, b1);

    const int lane = tid & 31;
    const int wid  = tid >> 5;      // n block: (NBLK/8)*wid
    const int grp  = lane >> 2;     // 0..7
    const int tig  = lane & 3;      // 0..3

    float c[2][NT][4];
    #pragma unroll
    for (int mt = 0; mt < 2; ++mt)
        #pragma unroll
        for (int nt = 0; nt < NT; ++nt)
            #pragma unroll
            for (int j = 0; j < 4; ++j) c[mt][nt][j] = 0.f;

    #pragma unroll
    for (int g = 0; g < 4; ++g) {
        if      (g == 0) asm volatile("cp.async.wait_group 3;\n");
        else if (g == 1) asm volatile("cp.async.wait_group 2;\n");
        else if (g == 2) asm volatile("cp.async.wait_group 1;\n");
        else             asm volatile("cp.async.wait_group 0;\n");
        __syncthreads();
        #pragma unroll
        for (int s2 = 0; s2 < 2; ++s2) {
            const int k0 = g * 16 + s2 * 8;
            uint32_t ah[2][4], al[2][4];
            #pragma unroll
            for (int mt = 0; mt < 2; ++mt) {
                const float* ar0 = a_s + (mt * 16 + grp) * 68 + k0 + tig;
                const float* ar1 = ar0 + 8 * 68;
                const float f[4] = { ar0[0], ar1[0], ar0[4], ar1[4] };
                #pragma unroll
                for (int j = 0; j < 4; ++j) {
                    ah[mt][j] = f2tf32(f[j]);
                    if (PREC == 3)
                        al[mt][j] = f2tf32(f[j] - __uint_as_float(ah[mt][j]));
                }
            }
            #pragma unroll
            for (int nt = 0; nt < NT; ++nt) {
                const float* br =
                    w_s + (wid * (NBLK / 8) + nt * 8 + grp) * 68 + k0 + tig;
                const float b0f = br[0], b1f = br[4];
                const uint32_t bh0 = f2tf32(b0f), bh1 = f2tf32(b1f);
                #pragma unroll
                for (int mt = 0; mt < 2; ++mt) {
                    MMA_TF32(c[mt][nt], ah[mt][0], ah[mt][1], ah[mt][2], ah[mt][3],
                             bh0, bh1);
                    if (PREC == 3) {
                        const uint32_t bl0 = f2tf32(b0f - __uint_as_float(bh0));
                        const uint32_t bl1 = f2tf32(b1f - __uint_as_float(bh1));
                        MMA_TF32(c[mt][nt], al[mt][0], al[mt][1], al[mt][2], al[mt][3],
                                 bh0, bh1);
                        MMA_TF32(c[mt][nt], ah[mt][0], ah[mt][1], ah[mt][2], ah[mt][3],
                                 bl0, bl1);
                    }
                }
            }
        }
    }

    // epilogue: rows mt*16+grp (+8), cols j0 + wid*(NBLK/8) + 8nt + 2tig (+1)
    #pragma unroll
    for (int mt = 0; mt < 2; ++mt) {
        const int m0 = split * BATCH + mt * 16 + grp;
        #pragma unroll
        for (int nt = 0; nt < NT; ++nt) {
            float* d0 = P + (size_t)m0 * N + j0 + wid * (NBLK / 8) + nt * 8 + 2 * tig;
            float* d1 = d0 + (size_t)8 * N;
            *reinterpret_cast<float2*>(d0) = make_float2(c[mt][nt][0], c[mt][nt][1]);
            *reinterpret_cast<float2*>(d1) = make_float2(c[mt][nt][2], c[mt][nt][3]);
        }
    }
}

// =====================================================================
// Gaussian pseudo-attention: one warp per (b,i), streams K/V (256 MB)
// with all 16 row loads batched up front (MLP=16). Folds mu/sigma
// split-K combine; accumulates LN(x) stats via atomics.
// =====================================================================
__global__ __launch_bounds__(256)
void gauss_kernel(const float* __restrict__ Kp,
                  const float* __restrict__ Vp,
                  const float* __restrict__ Qp,
                  const float* __restrict__ mu_b,
                  const float* __restrict__ sig_b)
{
    const int tid  = threadIdx.x;
    const int w    = blockIdx.x * 8 + (tid >> 5);
    const int lane = tid & 31;
    const int b = w >> 10;
    const int i = w & 1023;

    float mu = mu_b[i];
    float sg = sig_b[i];
    #pragma unroll
    for (int s = 0; s < MS_SPLIT; ++s) {
        mu += g_part[MU_OFF  + (s * BATCH + b) * NTOK + i];
        sg += g_part[SIG_OFF + (s * BATCH + b) * NTOK + i];
    }
    mu = tanhf(mu);
    const float coef = -0.5f / (sg * sg + 1e-8f);

    const float4* K4 = reinterpret_cast<const float4*>(Kp) + (size_t)w * (DDIM / 4);
    const float4* V4 = reinterpret_cast<const float4*>(Vp) + (size_t)w * (DDIM / 4);

    float4 kr[8], vr[8];
    #pragma unroll
    for (int it = 0; it < 8; ++it) kr[it] = __ldcs(&K4[it * 32 + lane]);
    #pragma unroll
    for (int it = 0; it < 8; ++it) vr[it] = __ldcs(&V4[it * 32 + lane]);

    float acc = 0.f;
    #pragma unroll
    for (int it = 0; it < 8; ++it) {
        float d;
        d = kr[it].x - mu; acc += __expf(coef * d * d) * vr[it].x;
        d = kr[it].y - mu; acc += __expf(coef * d * d) * vr[it].y;
        d = kr[it].z - mu; acc += __expf(coef * d * d) * vr[it].z;
        d = kr[it].w - mu; acc += __expf(coef * d * d) * vr[it].w;
    }
    #pragma unroll
    for (int o = 16; o; o >>= 1) acc += __shfl_xor_sync(0xffffffffu, acc, o);

    __shared__ float shv[8];
    if (lane == 0) {
        const float v = acc + Qp[w];
        g_x[w] = v;
        shv[tid >> 5] = v;
    }
    __syncthreads();
    if (tid < 32) {
        float v = (lane < 8) ? shv[lane] : 0.f;
        float s = v, ss = v * v;
        #pragma unroll
        for (int o = 4; o; o >>= 1) {
            s  += __shfl_xor_sync(0xffffffffu, s,  o);
            ss += __shfl_xor_sync(0xffffffffu, ss, o);
        }
        if (lane == 0) {
            atomicAdd(&g_xraw[2 * b],     s);
            atomicAdd(&g_xraw[2 * b + 1], ss);
        }
    }
}

// =====================================================================
// final combine: out = x + b2 + sum of F2_SPLIT partials   (32 x 1024)
// =====================================================================
__global__ void final_kernel(const float* __restrict__ b2,
                             float* __restrict__ out)
{
    const int t  = blockIdx.x * blockDim.x + threadIdx.x;   // 0..8191 float4s
    const int m  = t >> 8;
    const int j4 = t & 255;
    float4 s = reinterpret_cast<const float4*>(g_x)[t];
    const float4 bb = reinterpret_cast<const float4*>(b2)[j4];
    s.x += bb.x; s.y += bb.y; s.z += bb.z; s.w += bb.w;
    #pragma unroll
    for (int sp = 0; sp < F2_SPLIT; ++sp) {
        const float4 p = *reinterpret_cast<const float4*>(
            g_part + W2_OFF + (size_t)(sp * BATCH + m) * NTOK + j4 * 4);
        s.x += p.x; s.y += p.y; s.z += p.z; s.w += p.w;
    }
    reinterpret_cast<float4*>(out)[t] = s;
}

// =====================================================================
extern "C" void kernel_launch(void* const* d_in, const int* in_sizes, int n_in,
                              void* d_out, int out_size)
{
    const float* Q       = (const float*)d_in[0];
    const float* Kt      = (const float*)d_in[1];
    const float* Vt      = (const float*)d_in[2];
    const float* mu_w    = (const float*)d_in[3];
    const float* mu_b    = (const float*)d_in[4];
    const float* sigma_w = (const float*)d_in[5];
    const float* sigma_b = (const float*)d_in[6];
    const float* ffn_w1  = (const float*)d_in[7];
    const float* ffn_b1  = (const float*)d_in[8];
    const float* ffn_w2  = (const float*)d_in[9];
    const float* ffn_b2  = (const float*)d_in[10];
    const float* ln_ff_g = (const float*)d_in[11];
    const float* ln_ff_b = (const float*)d_in[12];
    const float* ln_q_g  = (const float*)d_in[13];
    const float* ln_q_b  = (const float*)d_in[14];
    float* out = (float*)d_out;

    cudaFuncSetAttribute((const void*)gemm_tc_kernel<0, 128, 3>,
                         cudaFuncAttributeMaxDynamicSharedMemorySize, GEMM_SMEM(128));
    cudaFuncSetAttribute((const void*)gemm_tc_kernel<1, 256, 1>,
                         cudaFuncAttributeMaxDynamicSharedMemorySize, GEMM_SMEM(256));
    cudaFuncSetAttribute((const void*)gemm_tc_kernel<2, 256, 1>,
                         cudaFuncAttributeMaxDynamicSharedMemorySize, GEMM_SMEM(256));

    // 1. Q row stats + zero x-stat accumulators
    stats_kernel<<<1, 1024>>>(Q);

    // 2. mu & sigma on LN(Q): 3xTF32 tensor cores, split-K 16 -> 256 blocks
    gemm_tc_kernel<0, 128, 3><<<dim3(NTOK / 128, MS_SPLIT, 2), 256, GEMM_SMEM(128)>>>(
        mu_w, sigma_w, NTOK, NTOK, MU_OFF, SIG_OFF - MU_OFF,
        Q, ln_q_g, ln_q_b, nullptr);

    // 3. Gaussian stream + mu/sigma combine + x-stat atomics
    gauss_kernel<<<(BATCH * NTOK) / 8, 256>>>(Kt, Vt, Q, mu_b, sigma_b);

    // 4. FFN GEMM 1 on LN(g_x), tf32 tensor cores, split-K 16
    gemm_tc_kernel<1, 256, 1><<<dim3(MFF / 256, F1_SPLIT, 1), 256, GEMM_SMEM(256)>>>(
        ffn_w1, ffn_w1, NTOK, MFF, W1_OFF, 0,
        nullptr, ln_ff_g, ln_ff_b, nullptr);

    // 5. FFN GEMM 2 on silu(partials + b1), tf32 tensor cores, split-K 64
    gemm_tc_kernel<2, 256, 1><<<dim3(NTOK / 256, F2_SPLIT, 1), 256, GEMM_SMEM(256)>>>(
        ffn_w2, ffn_w2, MFF, NTOK, W2_OFF, 0,
        nullptr, nullptr, nullptr, ffn_b1);

    // 6. out = x + b2 + sum of FFN2 partials
    final_kernel<<<64, 128>>>(ffn_b2, out);
}